// round 10
// baseline (speedup 1.0000x reference)
#include <cuda_runtime.h>
#include <cstdint>

#define S_DIM 384

// Fragment-layout operand buffers (permutations written by kernel 1):
// g_A: [MI=m/16 (768)][kf=k/8 (64)][512B frag]
// g_B: [NI=p/8 (1536)][kf (64)][256B frag]
// g_W2:[zg=zz/16 (8)][kf'=k'/8 (128)][512B frag]  (k' = d*32 + c)
__device__ float g_A[12288 * 512];
__device__ float g_B[12288 * 512];
__device__ float g_W2[128 * 1024];

// ---------------------------------------------------------------- helpers
__device__ __forceinline__ uint32_t smem_u32(const void* p) {
    uint32_t a;
    asm("{ .reg .u64 t; cvta.to.shared.u64 t, %1; cvt.u32.u64 %0, t; }" : "=r"(a) : "l"(p));
    return a;
}
__device__ __forceinline__ float tf32rn(float x) {
    uint32_t r; asm("cvt.rna.tf32.f32 %0, %1;" : "=r"(r) : "f"(x));
    return __uint_as_float(r);
}
__device__ __forceinline__ void lds128(uint32_t* v, uint32_t a) {
    asm volatile("ld.shared.v4.b32 {%0,%1,%2,%3}, [%4];"
                 : "=r"(v[0]), "=r"(v[1]), "=r"(v[2]), "=r"(v[3]) : "r"(a));
}
__device__ __forceinline__ void lds64(uint32_t* v, uint32_t a) {
    asm volatile("ld.shared.v2.b32 {%0,%1}, [%2];"
                 : "=r"(v[0]), "=r"(v[1]) : "r"(a));
}
__device__ __forceinline__ void sts32(uint32_t a, float v) {
    asm volatile("st.shared.b32 [%0], %1;" :: "r"(a), "f"(v) : "memory");
}
__device__ __forceinline__ void cp16(uint32_t dst, const float* src) {
    asm volatile("cp.async.cg.shared.global [%0], [%1], 16;" :: "r"(dst), "l"(src));
}
#define CP_COMMIT() asm volatile("cp.async.commit_group;" ::: "memory")
#define CP_WAIT2()  asm volatile("cp.async.wait_group 2;" ::: "memory")
#define CP_WAIT1()  asm volatile("cp.async.wait_group 1;" ::: "memory")
#define CP_WAIT0()  asm volatile("cp.async.wait_group 0;" ::: "memory")

// m16n8k8 tf32 MMA: D += A*B
__device__ __forceinline__ void mma8(float* d, const uint32_t* a, uint32_t b0, uint32_t b1) {
    asm volatile(
        "mma.sync.aligned.m16n8k8.row.col.f32.tf32.tf32.f32 "
        "{%0,%1,%2,%3}, {%4,%5,%6,%7}, {%8,%9}, {%0,%1,%2,%3};"
        : "+f"(d[0]), "+f"(d[1]), "+f"(d[2]), "+f"(d[3])
        : "r"(a[0]), "r"(a[1]), "r"(a[2]), "r"(a[3]), "r"(b0), "r"(b1));
}

// ---------------------------------------------------------------- kernel 1: LN + proj + W prep
// 1536 blocks: b -> (s = b>>2, n-slice of 128). W prep spread over blocks 0..511.
__global__ __launch_bounds__(256) void ln_proj_kernel(
    const float* __restrict__ m_si, const float* __restrict__ ln_g,
    const float* __restrict__ ln_b, const float* __restrict__ w_ab,
    const float* __restrict__ w_final)
{
    __shared__ float ws[64 * 33];
    __shared__ float a_s[32 * 130];
    __shared__ float b_s[32 * 130];

    int t = threadIdx.x, warp = t >> 5, lane = t & 31;
    int b = blockIdx.x;
    int s = b >> 2, n0 = (b & 3) * 128;

    if (b < 512) {   // W prep: g_W2 fragment layout, k' = d*32+c
        int i  = b * 256 + t;
        int kk = i >> 7, zz = i & 127;
        float v = tf32rn(w_final[zz * 1024 + (kk & 31) * 32 + (kk >> 5)]);
        int off = (zz >> 4) * 16384 + (kk >> 3) * 128
                + ((zz & 7) * 4 + (kk & 3)) * 4
                + ((zz >> 3) & 1) + ((kk >> 2) & 1) * 2;
        g_W2[off] = v;
    }

    for (int idx = t; idx < 64 * 32; idx += 256)
        ws[(idx >> 5) * 33 + (idx & 31)] = w_ab[idx];
    __syncthreads();

    float g = ln_g[lane], bb = ln_b[lane];

    for (int it = 0; it < 16; it++) {
        int nl = warp * 16 + it;
        float x = m_si[((size_t)(s * 512 + n0 + nl)) * 32 + lane];

        float sum = x;
        #pragma unroll
        for (int o = 16; o; o >>= 1) sum += __shfl_xor_sync(0xFFFFFFFFu, sum, o);
        float mu = sum * (1.0f / 32.0f);
        float dx = x - mu;
        float v = dx * dx;
        #pragma unroll
        for (int o = 16; o; o >>= 1) v += __shfl_xor_sync(0xFFFFFFFFu, v, o);
        float mn = dx * rsqrtf(v * (1.0f / 32.0f) + 1e-5f) * g + bb;

        float aa = 0.0f, ab = 0.0f;
        #pragma unroll
        for (int c = 0; c < 32; c++) {
            float mc = __shfl_sync(0xFFFFFFFFu, mn, c);
            aa += mc * ws[lane * 33 + c];
            ab += mc * ws[(lane + 32) * 33 + c];
        }
        a_s[lane * 130 + nl] = aa * (1.0f / 512.0f);
        b_s[lane * 130 + nl] = ab;
    }
    __syncthreads();

    // ---- coalesced fragment stores via inverse-permutation gather
    int kf0 = n0 >> 3;

    // A: 4096 words in [MI 2][kf 16][frag 128]; word = (c>>3&1) + 2*(n>>2&1)
    #pragma unroll
    for (int q = 0; q < 4; q++) {
        int oi  = q * 1024 + t * 4;
        int MIl = oi >> 11;
        int kfl = (oi >> 7) & 15;
        int ln4 = t & 31;
        float4 v;
        float* vp = &v.x;
        #pragma unroll
        for (int e = 0; e < 4; e++) {
            int c  = MIl * 16 + (e & 1) * 8 + (ln4 >> 2);
            int nl = kfl * 8 + ((e >> 1) & 1) * 4 + (ln4 & 3);
            vp[e] = tf32rn(a_s[c * 130 + nl]);
        }
        *reinterpret_cast<float4*>(g_A + (size_t)(s * 2 + MIl) * 8192
                                   + (kf0 + kfl) * 128 + (oi & 127)) = v;
    }

    // B: 4096 words in [NI 4][kf 16][frag 64]; word = (n>>2)&1
    #pragma unroll
    for (int q = 0; q < 4; q++) {
        int oi  = q * 1024 + t * 4;
        int NIl = oi >> 10;
        int kfl = (oi >> 6) & 15;
        float4 v;
        float* vp = &v.x;
        #pragma unroll
        for (int e = 0; e < 4; e++) {
            int f    = (t * 4 + e) & 63;
            int ln_  = f >> 1, word = f & 1;
            int c    = NIl * 8 + (ln_ >> 2);
            int nl   = kfl * 8 + word * 4 + (ln_ & 3);
            vp[e] = tf32rn(b_s[c * 130 + nl]);
        }
        *reinterpret_cast<float4*>(g_B + (size_t)(s * 4 + NIl) * 4096
                                   + (kf0 + kfl) * 64 + (oi & 63)) = v;
    }
}

// ---------------------------------------------------------------- kernel 2
// 256 threads, tile 128(m) x 128(p). SMEM: 3 stages x 32KB (A 16K + B 16K).
// Epilogue reuse: osm frag layout [kf' 128][pf 2][256B] = 64KB at 0;
// per-warp W stage (4-deep) at 65536 + w*4096 + buf*1024.  Total 98304.
#define STG     32768u
#define OFF_WS  65536u
#define SMEM2   98304

__device__ __forceinline__ void load_AB(uint32_t slot, int ch, int mi0, int ni0, int t) {
    #pragma unroll
    for (int q = 0; q < 4; q++) {                 // A: 1024 16B units
        int idx = t + q * 256;
        int MIi = idx >> 7, ksf = (idx >> 5) & 3, unit = idx & 31;
        cp16(slot + (uint32_t)idx * 16u,
             g_A + (size_t)(mi0 + MIi) * 8192 + (ch * 4 + ksf) * 128 + unit * 4);
    }
    #pragma unroll
    for (int q = 0; q < 4; q++) {                 // B: 1024 units
        int idx = t + q * 256;
        int NIl = idx >> 6, ksf = (idx >> 4) & 3, unit = idx & 15;
        cp16(slot + 16384u + (uint32_t)idx * 16u,
             g_B + (size_t)(ni0 + NIl) * 4096 + (ch * 4 + ksf) * 64 + unit * 4);
    }
}

__device__ __forceinline__ void load_Wc(uint32_t sb, int ch, int w, int lane) {
    uint32_t wsb = sb + OFF_WS + (uint32_t)w * 4096u + (uint32_t)(ch & 3) * 1024u;
    #pragma unroll
    for (int q = 0; q < 2; q++) {
        int idx = lane + q * 32;
        int kfl = idx >> 5, unit = idx & 31;
        cp16(wsb + (uint32_t)idx * 16u,
             g_W2 + (size_t)w * 16384 + (ch * 2 + kfl) * 128 + unit * 4);
    }
}

__global__ __launch_bounds__(256, 2) void opm_mma_kernel(
    const float* __restrict__ b_final, float* __restrict__ z)
{
    extern __shared__ char smem_raw[];
    uint32_t sb = smem_u32(smem_raw);

    int t = threadIdx.x, w = t >> 5, lane = t & 31;
    int g = lane >> 2, r = lane & 3;
    int wm = w >> 2, wn = w & 3;                 // 2(m) x 4(p) warps, 64x32 tiles
    int mi0 = blockIdx.y * 8;
    int ni0 = blockIdx.x * 16;
    uint32_t l16 = (uint32_t)lane * 16u, l8 = (uint32_t)lane * 8u;

    float acc[4][4][4];
    #pragma unroll
    for (int i = 0; i < 4; i++)
        #pragma unroll
        for (int j = 0; j < 4; j++)
            #pragma unroll
            for (int cc = 0; cc < 4; cc++) acc[i][j][cc] = 0.0f;

    // ---- mainloop: 16 chunks of k=32, 3-stage pipeline
    load_AB(sb + 0u * STG, 0, mi0, ni0, t); CP_COMMIT();
    load_AB(sb + 1u * STG, 1, mi0, ni0, t); CP_COMMIT();

    for (int s = 0; s < 16; s++) {
        if (s < 15) CP_WAIT1(); else CP_WAIT0();
        __syncthreads();

        uint32_t slot = sb + (uint32_t)(s % 3) * STG;
        uint32_t aBase = slot + (uint32_t)(wm * 16) * 512u;
        uint32_t bBase = slot + 16384u + (uint32_t)(wn * 16) * 256u;

        #pragma unroll
        for (int ks = 0; ks < 4; ks++) {
            uint32_t a[4][4], b[4][2];
            #pragma unroll
            for (int i = 0; i < 4; i++)
                lds128(a[i], aBase + (uint32_t)(i * 4 + ks) * 512u + l16);
            #pragma unroll
            for (int j = 0; j < 4; j++)
                lds64(b[j], bBase + (uint32_t)(j * 4 + ks) * 256u + l8);
            #pragma unroll
            for (int i = 0; i < 4; i++)
                #pragma unroll
                for (int j = 0; j < 4; j++)
                    mma8(acc[i][j], a[i], b[j][0], b[j][1]);
        }

        if (s + 2 < 16) {
            load_AB(sb + (uint32_t)((s + 2) % 3) * STG, s + 2, mi0, ni0, t);
            CP_COMMIT();
        }
    }
    __syncthreads();

    // ---- prefetch W chunks 0..2 (per-warp, 4-deep ring), spill o (frag layout)
    load_Wc(sb, 0, w, lane); CP_COMMIT();
    load_Wc(sb, 1, w, lane); CP_COMMIT();
    load_Wc(sb, 2, w, lane); CP_COMMIT();

    #pragma unroll
    for (int i = 0; i < 4; i++)
        #pragma unroll
        for (int j = 0; j < 4; j++)
            #pragma unroll
            for (int cc = 0; cc < 4; cc++) {
                int m = wm * 64 + i * 16 + g + ((cc & 2) ? 8 : 0);
                int p = wn * 32 + j * 8 + 2 * r + (cc & 1);
                int kp   = (p & 31) * 32 + (m & 31);             // k'
                int pair = ((m >> 5) << 2) | (p >> 5);           // 0..15
                int off = ((kp >> 3) * 2 + (pair >> 3)) * 256
                        + ((pair & 7) * 4 + (kp & 3)) * 8 + ((kp >> 2) & 1) * 4;
                sts32(sb + (uint32_t)off, tf32rn(acc[i][j][cc]));
            }
    __syncthreads();

    // ---- epilogue: z[zz][pair] = W' * o' (K=1024, 64 chunks of 16)
    float zacc[2][4];
    #pragma unroll
    for (int jj = 0; jj < 2; jj++)
        #pragma unroll
        for (int cc = 0; cc < 4; cc++) zacc[jj][cc] = 0.0f;

    for (int ch = 0; ch < 64; ch++) {
        if (ch < 62) CP_WAIT2();
        else if (ch == 62) CP_WAIT1();
        else CP_WAIT0();
        __syncwarp();

        uint32_t wsb = sb + OFF_WS + (uint32_t)w * 4096u + (uint32_t)(ch & 3) * 1024u;
        #pragma unroll
        for (int ks = 0; ks < 2; ks++) {
            uint32_t aw[4];
            lds128(aw, wsb + (uint32_t)ks * 512u + l16);
            #pragma unroll
            for (int jj = 0; jj < 2; jj++) {
                uint32_t b[2];
                lds64(b, sb + (uint32_t)(((ch * 2 + ks) * 2 + jj) * 256) + l8);
                mma8(zacc[jj], aw, b[0], b[1]);
            }
        }
        if (ch + 3 < 64) { load_Wc(sb, ch + 3, w, lane); CP_COMMIT(); }
    }
    __syncthreads();       // all warps done reading osm

    // ---- stage z (+bias) into smem [pair 16][zz 128], then coalesced stores
    float bf0 = b_final[w * 16 + g];
    float bf1 = b_final[w * 16 + g + 8];
    #pragma unroll
    for (int jj = 0; jj < 2; jj++)
        #pragma unroll
        for (int cc = 0; cc < 4; cc++) {
            int zz = w * 16 + g + ((cc & 2) ? 8 : 0);
            int pr = jj * 8 + 2 * r + (cc & 1);
            sts32(sb + (uint32_t)((pr * 128 + zz) * 4),
                  zacc[jj][cc] + ((cc & 2) ? bf1 : bf0));
        }
    __syncthreads();

    {
        int pr = t >> 4, zz0 = (t & 15) * 8;
        int ig = blockIdx.y * 4 + (pr >> 2);
        int jg = blockIdx.x * 4 + (pr & 3);
        float* dst = z + ((size_t)(ig * S_DIM + jg)) * 128 + zz0;
        uint32_t srcb = sb + (uint32_t)((pr * 128 + zz0) * 4);
        uint32_t v[4];
        lds128(v, srcb);
        *reinterpret_cast<float4*>(dst) =
            make_float4(__uint_as_float(v[0]), __uint_as_float(v[1]),
                        __uint_as_float(v[2]), __uint_as_float(v[3]));
        lds128(v, srcb + 16u);
        *reinterpret_cast<float4*>(dst + 4) =
            make_float4(__uint_as_float(v[0]), __uint_as_float(v[1]),
                        __uint_as_float(v[2]), __uint_as_float(v[3]));
    }
}

// ---------------------------------------------------------------- launch
extern "C" void kernel_launch(void* const* d_in, const int* in_sizes, int n_in,
                              void* d_out, int out_size)
{
    const float* m_si    = (const float*)d_in[0];
    const float* ln_g    = (const float*)d_in[1];
    const float* ln_b    = (const float*)d_in[2];
    const float* w_ab    = (const float*)d_in[3];
    const float* w_final = (const float*)d_in[4];
    const float* b_final = (const float*)d_in[5];
    float* z = (float*)d_out;
    (void)in_sizes; (void)n_in; (void)out_size;

    ln_proj_kernel<<<1536, 256>>>(m_si, ln_g, ln_b, w_ab, w_final);

    cudaFuncSetAttribute(opm_mma_kernel,
                         cudaFuncAttributeMaxDynamicSharedMemorySize, SMEM2);
    dim3 grid(96, 96);   // (p-tiles, m-tiles), 128x128 each
    opm_mma_kernel<<<grid, 256, SMEM2>>>(b_final, z);
}

// round 11
// speedup vs baseline: 1.8591x; 1.8591x over previous
#include <cuda_runtime.h>
#include <cstdint>

#define S_DIM 384

// fp16 fragment-layout operand buffers (packed half2 words, written by kernel 1):
// g_Ah: [MI=m/16 (768)][kf2=k/16 (32)][128 w]  A-frag m16n8k16 (m=i*32+c, k=n)
// g_Bh: [NI=p/8 (1536)][kf2 (32)][64 w]        B-frag            (p=j*32+d)
// g_Wh: [zg=zz/16 (8)][kf2'=k'/16 (64)][128 w] A-frag for W, k' = c*32+d (= k identity)
__device__ unsigned int g_Ah[768 * 32 * 128];
__device__ unsigned int g_Bh[1536 * 32 * 64];
__device__ unsigned int g_Wh[8 * 64 * 128];

// ---------------------------------------------------------------- helpers
__device__ __forceinline__ uint32_t smem_u32(const void* p) {
    uint32_t a;
    asm("{ .reg .u64 t; cvta.to.shared.u64 t, %1; cvt.u32.u64 %0, t; }" : "=r"(a) : "l"(p));
    return a;
}
__device__ __forceinline__ uint32_t pack_h2(float lo, float hi) {
    uint32_t u;   // cvt.rn.f16x2.f32 d, a, b  ->  d.hi = cvt(a), d.lo = cvt(b)
    asm("cvt.rn.f16x2.f32 %0, %1, %2;" : "=r"(u) : "f"(hi), "f"(lo));
    return u;
}
__device__ __forceinline__ void lds128(uint32_t* v, uint32_t a) {
    asm volatile("ld.shared.v4.b32 {%0,%1,%2,%3}, [%4];"
                 : "=r"(v[0]), "=r"(v[1]), "=r"(v[2]), "=r"(v[3]) : "r"(a));
}
__device__ __forceinline__ void lds64(uint32_t* v, uint32_t a) {
    asm volatile("ld.shared.v2.b32 {%0,%1}, [%2];"
                 : "=r"(v[0]), "=r"(v[1]) : "r"(a));
}
__device__ __forceinline__ void sts32(uint32_t a, uint32_t v) {
    asm volatile("st.shared.b32 [%0], %1;" :: "r"(a), "r"(v) : "memory");
}
__device__ __forceinline__ void cp16(uint32_t dst, const void* src) {
    asm volatile("cp.async.cg.shared.global [%0], [%1], 16;" :: "r"(dst), "l"(src));
}
#define CP_COMMIT() asm volatile("cp.async.commit_group;" ::: "memory")
#define CP_WAIT1()  asm volatile("cp.async.wait_group 1;" ::: "memory")
#define CP_WAIT0()  asm volatile("cp.async.wait_group 0;" ::: "memory")

// m16n8k16 fp16 MMA, f32 accum: D += A*B
__device__ __forceinline__ void mma16(float* d, const uint32_t* a, uint32_t b0, uint32_t b1) {
    asm volatile(
        "mma.sync.aligned.m16n8k16.row.col.f32.f16.f16.f32 "
        "{%0,%1,%2,%3}, {%4,%5,%6,%7}, {%8,%9}, {%0,%1,%2,%3};"
        : "+f"(d[0]), "+f"(d[1]), "+f"(d[2]), "+f"(d[3])
        : "r"(a[0]), "r"(a[1]), "r"(a[2]), "r"(a[3]), "r"(b0), "r"(b1));
}

// ---------------------------------------------------------------- kernel 1: LN + proj + W prep
// 1536 blocks: b -> (s = b>>2, n-slice of 128). W prep on blocks 0..255.
__global__ __launch_bounds__(256) void ln_proj_kernel(
    const float* __restrict__ m_si, const float* __restrict__ ln_g,
    const float* __restrict__ ln_b, const float* __restrict__ w_ab,
    const float* __restrict__ w_final)
{
    __shared__ float ws[64 * 33];
    __shared__ float a_s[32 * 130];
    __shared__ float b_s[32 * 130];

    int t = threadIdx.x, warp = t >> 5, lane = t & 31;
    int b = blockIdx.x;
    int s = b >> 2, n0 = (b & 3) * 128;

    if (b < 256) {   // W prep: g_Wh A-frag layout, k' = k (identity)
        int i = b * 256 + t;                     // word index 0..65535
        int zg = i >> 13, kf2 = (i >> 7) & 63, waddr = i & 127;
        int wl = waddr >> 2, wi = waddr & 3;
        int zz = zg * 16 + (wi & 1) * 8 + (wl >> 2);
        int k0 = kf2 * 16 + ((wi >> 1) & 1) * 8 + (wl & 3) * 2;
        g_Wh[i] = pack_h2(w_final[zz * 1024 + k0], w_final[zz * 1024 + k0 + 1]);
    }

    for (int idx = t; idx < 64 * 32; idx += 256)
        ws[(idx >> 5) * 33 + (idx & 31)] = w_ab[idx];
    __syncthreads();

    float g = ln_g[lane], bb = ln_b[lane];

    for (int it = 0; it < 16; it++) {
        int nl = warp * 16 + it;
        float x = m_si[((size_t)(s * 512 + n0 + nl)) * 32 + lane];

        float sum = x;
        #pragma unroll
        for (int o = 16; o; o >>= 1) sum += __shfl_xor_sync(0xFFFFFFFFu, sum, o);
        float mu = sum * (1.0f / 32.0f);
        float dx = x - mu;
        float v = dx * dx;
        #pragma unroll
        for (int o = 16; o; o >>= 1) v += __shfl_xor_sync(0xFFFFFFFFu, v, o);
        float mn = dx * rsqrtf(v * (1.0f / 32.0f) + 1e-5f) * g + bb;

        float aa = 0.0f, ab = 0.0f;
        #pragma unroll
        for (int c = 0; c < 32; c++) {
            float mc = __shfl_sync(0xFFFFFFFFu, mn, c);
            aa += mc * ws[lane * 33 + c];
            ab += mc * ws[(lane + 32) * 33 + c];
        }
        a_s[lane * 130 + nl] = aa;               // 1/512 folded at spill now
        b_s[lane * 130 + nl] = ab;
    }
    __syncthreads();

    int kf0 = n0 >> 4;      // global kf2 base (8 per block)

    // ---- A gather: 2048 words -> 512 uint4 stores
    #pragma unroll
    for (int q = 0; q < 2; q++) {
        int idx4 = q * 256 + t;
        int wb = idx4 * 4;
        int MIl = wb >> 10, rem = wb & 1023;
        int kf2l = rem >> 7, waddr = rem & 127;
        int wl = waddr >> 2;
        uint4 v;
        uint32_t* vp = &v.x;
        #pragma unroll
        for (int wi = 0; wi < 4; wi++) {
            int c  = MIl * 16 + (wi & 1) * 8 + (wl >> 2);
            int nl = kf2l * 16 + ((wi >> 1) & 1) * 8 + (wl & 3) * 2;
            vp[wi] = pack_h2(a_s[c * 130 + nl], a_s[c * 130 + nl + 1]);
        }
        *reinterpret_cast<uint4*>(
            g_Ah + ((size_t)(s * 2 + MIl) * 32 + kf0 + kf2l) * 128 + waddr) = v;
    }

    // ---- B gather: 2048 words -> 512 uint4 stores
    #pragma unroll
    for (int q = 0; q < 2; q++) {
        int idx4 = q * 256 + t;
        int wb = idx4 * 4;
        int NIl = wb >> 9, rem = wb & 511;
        int kf2l = rem >> 6, waddr = rem & 63;
        uint4 v;
        uint32_t* vp = &v.x;
        #pragma unroll
        for (int e = 0; e < 4; e++) {
            int wd = waddr + e;
            int wl = wd >> 1, wi = wd & 1;
            int d_row = NIl * 8 + (wl >> 2);
            int nl = kf2l * 16 + wi * 8 + (wl & 3) * 2;
            vp[e] = pack_h2(b_s[d_row * 130 + nl], b_s[d_row * 130 + nl + 1]);
        }
        *reinterpret_cast<uint4*>(
            g_Bh + ((size_t)(s * 4 + NIl) * 32 + kf0 + kf2l) * 64 + waddr) = v;
    }
}

// ---------------------------------------------------------------- kernel 2
// 256 threads, tile 128(m) x 128(p), fp16 mainloop + epilogue.
// SMEM: 3 stages x 32KB (A 16K + B 16K) = 98304.
// Epilogue reuse: osm o'-frags [kf2' 64][pf 2][272B] = 34816 at 0;
// per-warp W stage (2-buf) at 34816 + w*2048 + buf*1024.
#define STG     32768u
#define OFF_WS  34816u
#define SMEM2   98304

__device__ __forceinline__ void load_AB(uint32_t slot, int ch, int mi0, int ni0, int t) {
    #pragma unroll
    for (int q = 0; q < 4; q++) {                 // A: 1024 16B units
        int idx = t + q * 256;
        int MIi = idx >> 7, kf2l = (idx >> 5) & 3, unit = idx & 31;
        cp16(slot + (uint32_t)idx * 16u,
             g_Ah + ((size_t)(mi0 + MIi) * 32 + ch * 4 + kf2l) * 128 + unit * 4);
    }
    #pragma unroll
    for (int q = 0; q < 4; q++) {                 // B: 1024 units
        int idx = t + q * 256;
        int NIl = idx >> 6, kf2l = (idx >> 4) & 3, unit = idx & 15;
        cp16(slot + 16384u + (uint32_t)idx * 16u,
             g_Bh + ((size_t)(ni0 + NIl) * 32 + ch * 4 + kf2l) * 64 + unit * 4);
    }
}

__device__ __forceinline__ void load_Wc(uint32_t sb, int ch, int buf, int w, int lane) {
    uint32_t wsb = sb + OFF_WS + (uint32_t)w * 2048u + (buf ? 1024u : 0u);
    #pragma unroll
    for (int q = 0; q < 2; q++) {
        int idx = lane + q * 32;
        int kfl = idx >> 5, unit = idx & 31;
        cp16(wsb + (uint32_t)idx * 16u,
             g_Wh + ((size_t)w * 64 + ch * 2 + kfl) * 128 + unit * 4);
    }
}

__global__ __launch_bounds__(256, 2) void opm_mma_kernel(
    const float* __restrict__ b_final, float* __restrict__ z)
{
    extern __shared__ char smem_raw[];
    uint32_t sb = smem_u32(smem_raw);

    int t = threadIdx.x, w = t >> 5, lane = t & 31;
    int g = lane >> 2, r = lane & 3;
    int wm = w >> 2, wn = w & 3;                 // 2(m) x 4(p) warps, 64x32 tiles
    int mi0 = blockIdx.y * 8;
    int ni0 = blockIdx.x * 16;
    uint32_t l16 = (uint32_t)lane * 16u, l8 = (uint32_t)lane * 8u;

    float acc[4][4][4];
    #pragma unroll
    for (int i = 0; i < 4; i++)
        #pragma unroll
        for (int j = 0; j < 4; j++)
            #pragma unroll
            for (int cc = 0; cc < 4; cc++) acc[i][j][cc] = 0.0f;

    // ---- mainloop: 8 chunks of k=64 (4 kf2 steps), 3-stage pipeline
    load_AB(sb + 0u * STG, 0, mi0, ni0, t); CP_COMMIT();
    load_AB(sb + 1u * STG, 1, mi0, ni0, t); CP_COMMIT();

    for (int s = 0; s < 8; s++) {
        if (s < 7) CP_WAIT1(); else CP_WAIT0();
        __syncthreads();

        uint32_t slot = sb + (uint32_t)(s % 3) * STG;

        #pragma unroll
        for (int ks = 0; ks < 4; ks++) {
            uint32_t a[4][4], bfr[4][2];
            #pragma unroll
            for (int i = 0; i < 4; i++)
                lds128(a[i], slot + (uint32_t)((wm * 4 + i) * 4 + ks) * 512u + l16);
            #pragma unroll
            for (int j = 0; j < 4; j++)
                lds64(bfr[j], slot + 16384u
                              + (uint32_t)((wn * 4 + j) * 4 + ks) * 256u + l8);
            #pragma unroll
            for (int i = 0; i < 4; i++)
                #pragma unroll
                for (int j = 0; j < 4; j++)
                    mma16(acc[i][j], a[i], bfr[j][0], bfr[j][1]);
        }

        if (s + 2 < 8) {
            load_AB(sb + (uint32_t)((s + 2) % 3) * STG, s + 2, mi0, ni0, t);
            CP_COMMIT();
        }
    }
    __syncthreads();

    // ---- prefetch W chunks 0,1 (per-warp 2-buf), spill o' (fp16 frags, 1/512 fold)
    load_Wc(sb, 0, 0, w, lane); CP_COMMIT();
    load_Wc(sb, 1, 1, w, lane); CP_COMMIT();

    const float sc = 1.0f / 512.0f;
    #pragma unroll
    for (int i = 0; i < 4; i++)
        #pragma unroll
        for (int j = 0; j < 4; j++)
            #pragma unroll
            for (int ccp = 0; ccp < 2; ccp++) {
                int m  = wm * 64 + i * 16 + g + ccp * 8;
                int pair = ((m >> 5) << 2) | wn;              // p0>>5 == wn
                int kf2p = (m & 31) * 2 + ((j >> 1) & 1);
                int lane_b = (pair & 7) * 4 + r;
                int addr = (kf2p * 2 + (pair >> 3)) * 272 + lane_b * 8 + (j & 1) * 4;
                sts32(sb + (uint32_t)addr,
                      pack_h2(acc[i][j][ccp * 2] * sc, acc[i][j][ccp * 2 + 1] * sc));
            }
    __syncthreads();

    // ---- epilogue: z[zz][pair] = W * o' (K=1024, 32 chunks of k'=32)
    float zacc[2][4];
    #pragma unroll
    for (int jj = 0; jj < 2; jj++)
        #pragma unroll
        for (int cc = 0; cc < 4; cc++) zacc[jj][cc] = 0.0f;

    for (int ch = 0; ch < 32; ch++) {
        int buf = ch & 1;
        if (ch < 31) CP_WAIT1(); else CP_WAIT0();
        __syncwarp();

        uint32_t wsb = sb + OFF_WS + (uint32_t)w * 2048u + (buf ? 1024u : 0u);
        #pragma unroll
        for (int ks = 0; ks < 2; ks++) {
            uint32_t aw[4];
            lds128(aw, wsb + (uint32_t)ks * 512u + l16);
            #pragma unroll
            for (int jj = 0; jj < 2; jj++) {
                uint32_t bfr[2];
                lds64(bfr, sb + (uint32_t)(((ch * 2 + ks) * 2 + jj) * 272) + l8);
                mma16(zacc[jj], aw, bfr[0], bfr[1]);
            }
        }
        if (ch + 2 < 32) { load_Wc(sb, ch + 2, buf, w, lane); CP_COMMIT(); }
    }

    // ---- write z (+bias), R9-style direct stores
    float bf0 = b_final[w * 16 + g];
    float bf1 = b_final[w * 16 + g + 8];
    #pragma unroll
    for (int jj = 0; jj < 2; jj++)
        #pragma unroll
        for (int cc = 0; cc < 4; cc++) {
            int zz = w * 16 + g + ((cc & 2) ? 8 : 0);
            int pr = jj * 8 + 2 * r + (cc & 1);              // pair 0..15
            int ig = blockIdx.y * 4 + (pr >> 2);
            int jg = blockIdx.x * 4 + (pr & 3);
            z[((size_t)(ig * S_DIM + jg)) * 128 + zz] =
                zacc[jj][cc] + ((cc & 2) ? bf1 : bf0);
        }
}

// ---------------------------------------------------------------- launch
extern "C" void kernel_launch(void* const* d_in, const int* in_sizes, int n_in,
                              void* d_out, int out_size)
{
    const float* m_si    = (const float*)d_in[0];
    const float* ln_g    = (const float*)d_in[1];
    const float* ln_b    = (const float*)d_in[2];
    const float* w_ab    = (const float*)d_in[3];
    const float* w_final = (const float*)d_in[4];
    const float* b_final = (const float*)d_in[5];
    float* z = (float*)d_out;
    (void)in_sizes; (void)n_in; (void)out_size;

    ln_proj_kernel<<<1536, 256>>>(m_si, ln_g, ln_b, w_ab, w_final);

    cudaFuncSetAttribute(opm_mma_kernel,
                         cudaFuncAttributeMaxDynamicSharedMemorySize, SMEM2);
    dim3 grid(96, 96);   // (p-tiles, m-tiles), 128x128 each
    opm_mma_kernel<<<grid, 96 == 0 ? 256 : 256, SMEM2>>>(b_final, z);
    // (grid unchanged; 256 threads, 2 CTAs/SM)
}

// round 13
// speedup vs baseline: 2.1082x; 1.1340x over previous
#include <cuda_runtime.h>
#include <cstdint>

#define S_DIM 384

// fp16 fragment-layout operand buffers (packed half2 words, written by kernel 1):
// g_Ah: [MI=m/16 (768)][kf2=k/16 (32)][128 w]  A-frag m16n8k16 (m=i*32+c, k=n)
// g_Bh: [NI=p/8 (1536)][kf2 (32)][64 w]        B-frag            (p=j*32+d)
// g_Wh: [zg=zz/16 (8)][kf2'=k'/16 (64)][128 w] A-frag for W, k' = c*32+d (= k identity)
__device__ unsigned int g_Ah[768 * 32 * 128];
__device__ unsigned int g_Bh[1536 * 32 * 64];
__device__ unsigned int g_Wh[8 * 64 * 128];

// ---------------------------------------------------------------- helpers
__device__ __forceinline__ uint32_t smem_u32(const void* p) {
    uint32_t a;
    asm("{ .reg .u64 t; cvta.to.shared.u64 t, %1; cvt.u32.u64 %0, t; }" : "=r"(a) : "l"(p));
    return a;
}
__device__ __forceinline__ uint32_t pack_h2(float lo, float hi) {
    uint32_t u;
    asm("cvt.rn.f16x2.f32 %0, %1, %2;" : "=r"(u) : "f"(hi), "f"(lo));
    return u;
}
__device__ __forceinline__ void lds128(uint32_t* v, uint32_t a) {
    asm volatile("ld.shared.v4.b32 {%0,%1,%2,%3}, [%4];"
                 : "=r"(v[0]), "=r"(v[1]), "=r"(v[2]), "=r"(v[3]) : "r"(a));
}
__device__ __forceinline__ void lds64(uint32_t* v, uint32_t a) {
    asm volatile("ld.shared.v2.b32 {%0,%1}, [%2];"
                 : "=r"(v[0]), "=r"(v[1]) : "r"(a));
}
__device__ __forceinline__ void sts32(uint32_t a, uint32_t v) {
    asm volatile("st.shared.b32 [%0], %1;" :: "r"(a), "r"(v) : "memory");
}
__device__ __forceinline__ void cp16(uint32_t dst, const void* src) {
    asm volatile("cp.async.cg.shared.global [%0], [%1], 16;" :: "r"(dst), "l"(src));
}
#define CP_COMMIT() asm volatile("cp.async.commit_group;" ::: "memory")
#define CP_WAIT1()  asm volatile("cp.async.wait_group 1;" ::: "memory")
#define CP_WAIT0()  asm volatile("cp.async.wait_group 0;" ::: "memory")

// m16n8k16 fp16 MMA, f32 accum: D += A*B
__device__ __forceinline__ void mma16(float* d, const uint32_t* a, uint32_t b0, uint32_t b1) {
    asm volatile(
        "mma.sync.aligned.m16n8k16.row.col.f32.f16.f16.f32 "
        "{%0,%1,%2,%3}, {%4,%5,%6,%7}, {%8,%9}, {%0,%1,%2,%3};"
        : "+f"(d[0]), "+f"(d[1]), "+f"(d[2]), "+f"(d[3])
        : "r"(a[0]), "r"(a[1]), "r"(a[2]), "r"(a[3]), "r"(b0), "r"(b1));
}

// ---------------------------------------------------------------- kernel 1: LN + proj + W prep
// (unchanged from round 11)
__global__ __launch_bounds__(256) void ln_proj_kernel(
    const float* __restrict__ m_si, const float* __restrict__ ln_g,
    const float* __restrict__ ln_b, const float* __restrict__ w_ab,
    const float* __restrict__ w_final)
{
    __shared__ float ws[64 * 33];
    __shared__ float a_s[32 * 130];
    __shared__ float b_s[32 * 130];

    int t = threadIdx.x, warp = t >> 5, lane = t & 31;
    int b = blockIdx.x;
    int s = b >> 2, n0 = (b & 3) * 128;

    if (b < 256) {   // W prep: g_Wh A-frag layout, k' = k (identity)
        int i = b * 256 + t;
        int zg = i >> 13, kf2 = (i >> 7) & 63, waddr = i & 127;
        int wl = waddr >> 2, wi = waddr & 3;
        int zz = zg * 16 + (wi & 1) * 8 + (wl >> 2);
        int k0 = kf2 * 16 + ((wi >> 1) & 1) * 8 + (wl & 3) * 2;
        g_Wh[i] = pack_h2(w_final[zz * 1024 + k0], w_final[zz * 1024 + k0 + 1]);
    }

    for (int idx = t; idx < 64 * 32; idx += 256)
        ws[(idx >> 5) * 33 + (idx & 31)] = w_ab[idx];
    __syncthreads();

    float g = ln_g[lane], bb = ln_b[lane];

    for (int it = 0; it < 16; it++) {
        int nl = warp * 16 + it;
        float x = m_si[((size_t)(s * 512 + n0 + nl)) * 32 + lane];

        float sum = x;
        #pragma unroll
        for (int o = 16; o; o >>= 1) sum += __shfl_xor_sync(0xFFFFFFFFu, sum, o);
        float mu = sum * (1.0f / 32.0f);
        float dx = x - mu;
        float v = dx * dx;
        #pragma unroll
        for (int o = 16; o; o >>= 1) v += __shfl_xor_sync(0xFFFFFFFFu, v, o);
        float mn = dx * rsqrtf(v * (1.0f / 32.0f) + 1e-5f) * g + bb;

        float aa = 0.0f, ab = 0.0f;
        #pragma unroll
        for (int c = 0; c < 32; c++) {
            float mc = __shfl_sync(0xFFFFFFFFu, mn, c);
            aa += mc * ws[lane * 33 + c];
            ab += mc * ws[(lane + 32) * 33 + c];
        }
        a_s[lane * 130 + nl] = aa;
        b_s[lane * 130 + nl] = ab;
    }
    __syncthreads();

    int kf0 = n0 >> 4;

    #pragma unroll
    for (int q = 0; q < 2; q++) {
        int idx4 = q * 256 + t;
        int wb = idx4 * 4;
        int MIl = wb >> 10, rem = wb & 1023;
        int kf2l = rem >> 7, waddr = rem & 127;
        int wl = waddr >> 2;
        uint4 v;
        uint32_t* vp = &v.x;
        #pragma unroll
        for (int wi = 0; wi < 4; wi++) {
            int c  = MIl * 16 + (wi & 1) * 8 + (wl >> 2);
            int nl = kf2l * 16 + ((wi >> 1) & 1) * 8 + (wl & 3) * 2;
            vp[wi] = pack_h2(a_s[c * 130 + nl], a_s[c * 130 + nl + 1]);
        }
        *reinterpret_cast<uint4*>(
            g_Ah + ((size_t)(s * 2 + MIl) * 32 + kf0 + kf2l) * 128 + waddr) = v;
    }

    #pragma unroll
    for (int q = 0; q < 2; q++) {
        int idx4 = q * 256 + t;
        int wb = idx4 * 4;
        int NIl = wb >> 9, rem = wb & 511;
        int kf2l = rem >> 6, waddr = rem & 63;
        uint4 v;
        uint32_t* vp = &v.x;
        #pragma unroll
        for (int e = 0; e < 4; e++) {
            int wd = waddr + e;
            int wl = wd >> 1, wi = wd & 1;
            int d_row = NIl * 8 + (wl >> 2);
            int nl = kf2l * 16 + wi * 8 + (wl & 3) * 2;
            vp[e] = pack_h2(b_s[d_row * 130 + nl], b_s[d_row * 130 + nl + 1]);
        }
        *reinterpret_cast<uint4*>(
            g_Bh + ((size_t)(s * 4 + NIl) * 32 + kf0 + kf2l) * 64 + waddr) = v;
    }
}

// ---------------------------------------------------------------- kernel 2
// 128 threads, 4 warps (2m x 2p), warp tile 64x64. CTA tile 128x128.
// SMEM: 3 stages x 32KB = 98304.
// Epilogue reuse: osm o'-frags [kf2' 64][pf 2][272B] = 34816 at 0;
// per-warp W stage (2-buf of 4KB) at 34816 + w*8192 + buf*4096.
#define STG     32768u
#define OFF_WS  34816u
#define SMEM2   98304

__device__ __forceinline__ void load_AB(uint32_t slot, int ch, int mi0, int ni0, int t) {
    #pragma unroll
    for (int q = 0; q < 8; q++) {                 // A: 1024 16B units
        int idx = t + q * 128;
        int MIi = idx >> 7, kf2l = (idx >> 5) & 3, unit = idx & 31;
        cp16(slot + (uint32_t)idx * 16u,
             g_Ah + ((size_t)(mi0 + MIi) * 32 + ch * 4 + kf2l) * 128 + unit * 4);
    }
    #pragma unroll
    for (int q = 0; q < 8; q++) {                 // B: 1024 units
        int idx = t + q * 128;
        int NIl = idx >> 6, kf2l = (idx >> 4) & 3, unit = idx & 15;
        cp16(slot + 16384u + (uint32_t)idx * 16u,
             g_Bh + ((size_t)(ni0 + NIl) * 32 + ch * 4 + kf2l) * 64 + unit * 4);
    }
}

// W stage layout per chunk (k'=64): [zi 2][ks 4][512B] = 4KB per warp buffer.
// zi stride in the stage = 2048 bytes (128 units of 16B).
__device__ __forceinline__ void load_Wc(uint32_t sb, int ch, int buf, int w, int lane) {
    uint32_t wsb = sb + OFF_WS + (uint32_t)w * 8192u + (buf ? 4096u : 0u);
    #pragma unroll
    for (int q = 0; q < 8; q++) {
        int idx = lane + q * 32;                  // 0..255 16B units
        cp16(wsb + (uint32_t)idx * 16u,
             g_Wh + ((size_t)(2 * w + (idx >> 7)) * 64 + ch * 4 + ((idx >> 5) & 3)) * 128
                  + (idx & 31) * 4);
    }
}

__global__ __launch_bounds__(128, 2) void opm_mma_kernel(
    const float* __restrict__ b_final, float* __restrict__ z)
{
    extern __shared__ char smem_raw[];
    uint32_t sb = smem_u32(smem_raw);

    int t = threadIdx.x, w = t >> 5, lane = t & 31;
    int g = lane >> 2, r = lane & 3;
    int wm = w >> 1, wn = w & 1;                 // 2(m) x 2(p) warps, 64x64 tiles
    int mi0 = blockIdx.y * 8;
    int ni0 = blockIdx.x * 16;
    uint32_t l16 = (uint32_t)lane * 16u, l8 = (uint32_t)lane * 8u;

    float acc[4][8][4];
    #pragma unroll
    for (int i = 0; i < 4; i++)
        #pragma unroll
        for (int j = 0; j < 8; j++)
            #pragma unroll
            for (int cc = 0; cc < 4; cc++) acc[i][j][cc] = 0.0f;

    // ---- mainloop: 8 chunks of k=64 (4 kf2 steps), 3-stage pipeline
    load_AB(sb + 0u * STG, 0, mi0, ni0, t); CP_COMMIT();
    load_AB(sb + 1u * STG, 1, mi0, ni0, t); CP_COMMIT();

    for (int s = 0; s < 8; s++) {
        if (s < 7) CP_WAIT1(); else CP_WAIT0();
        __syncthreads();

        uint32_t slot = sb + (uint32_t)(s % 3) * STG;

        #pragma unroll
        for (int ks = 0; ks < 4; ks++) {
            uint32_t a[4][4], bfr[8][2];
            #pragma unroll
            for (int i = 0; i < 4; i++)
                lds128(a[i], slot + (uint32_t)((wm * 4 + i) * 4 + ks) * 512u + l16);
            #pragma unroll
            for (int j = 0; j < 8; j++)
                lds64(bfr[j], slot + 16384u
                              + (uint32_t)((wn * 8 + j) * 4 + ks) * 256u + l8);
            #pragma unroll
            for (int i = 0; i < 4; i++)
                #pragma unroll
                for (int j = 0; j < 8; j++)
                    mma16(acc[i][j], a[i], bfr[j][0], bfr[j][1]);
        }

        if (s + 2 < 8) {
            load_AB(sb + (uint32_t)((s + 2) % 3) * STG, s + 2, mi0, ni0, t);
            CP_COMMIT();
        }
    }
    __syncthreads();

    // ---- prefetch W chunks 0,1 (per-warp 2-buf), spill o' (fp16 frags, 1/512)
    load_Wc(sb, 0, 0, w, lane); CP_COMMIT();
    load_Wc(sb, 1, 1, w, lane); CP_COMMIT();

    const float sc = 1.0f / 512.0f;
    #pragma unroll
    for (int i = 0; i < 4; i++)
        #pragma unroll
        for (int j = 0; j < 8; j++)
            #pragma unroll
            for (int ccp = 0; ccp < 2; ccp++) {
                int m = wm * 64 + i * 16 + g + ccp * 8;
                int p = wn * 64 + j * 8 + 2 * r;          // cc&1 is packed in half2
                int pair = ((m >> 5) << 2) | (p >> 5);
                int kf2p = (m & 31) * 2 + ((j >> 1) & 1);
                int lane_b = (pair & 7) * 4 + r;
                int addr = (kf2p * 2 + (pair >> 3)) * 272 + lane_b * 8 + (j & 1) * 4;
                sts32(sb + (uint32_t)addr,
                      pack_h2(acc[i][j][ccp * 2] * sc, acc[i][j][ccp * 2 + 1] * sc));
            }
    __syncthreads();

    // ---- epilogue: z[zz][pair] = W * o' (K=1024, 16 chunks of k'=64)
    // warp w: zz rows w*32..+31 (zi 2 tiles), both pair tiles (pf 2).
    float zacc[2][2][4];
    #pragma unroll
    for (int zi = 0; zi < 2; zi++)
        #pragma unroll
        for (int pf = 0; pf < 2; pf++)
            #pragma unroll
            for (int cc = 0; cc < 4; cc++) zacc[zi][pf][cc] = 0.0f;

    for (int ch = 0; ch < 16; ch++) {
        int buf = ch & 1;
        if (ch < 15) CP_WAIT1(); else CP_WAIT0();
        __syncwarp();

        uint32_t wsb = sb + OFF_WS + (uint32_t)w * 8192u + (buf ? 4096u : 0u);
        #pragma unroll
        for (int ks = 0; ks < 4; ks++) {
            uint32_t aw[2][4], bfr[2][2];
            #pragma unroll
            for (int zi = 0; zi < 2; zi++)
                lds128(aw[zi], wsb + (uint32_t)(zi * 2048 + ks * 512) + l16);  // FIX: zi*2048
            #pragma unroll
            for (int pf = 0; pf < 2; pf++)
                lds64(bfr[pf], sb + (uint32_t)(((ch * 4 + ks) * 2 + pf) * 272) + l8);
            #pragma unroll
            for (int zi = 0; zi < 2; zi++)
                #pragma unroll
                for (int pf = 0; pf < 2; pf++)
                    mma16(zacc[zi][pf], aw[zi], bfr[pf][0], bfr[pf][1]);
        }
        if (ch + 2 < 16) { load_Wc(sb, ch + 2, buf, w, lane); CP_COMMIT(); }
    }

    // ---- write z (+bias)
    float bf[2][2];
    #pragma unroll
    for (int zi = 0; zi < 2; zi++) {
        bf[zi][0] = b_final[w * 32 + zi * 16 + g];
        bf[zi][1] = b_final[w * 32 + zi * 16 + g + 8];
    }
    #pragma unroll
    for (int zi = 0; zi < 2; zi++)
        #pragma unroll
        for (int pf = 0; pf < 2; pf++)
            #pragma unroll
            for (int cc = 0; cc < 4; cc++) {
                int zz = w * 32 + zi * 16 + g + ((cc & 2) ? 8 : 0);
                int pr = pf * 8 + 2 * r + (cc & 1);
                int ig = blockIdx.y * 4 + (pr >> 2);
                int jg = blockIdx.x * 4 + (pr & 3);
                z[((size_t)(ig * S_DIM + jg)) * 128 + zz] =
                    zacc[zi][pf][cc] + bf[zi][(cc >> 1) & 1];
            }
}

// ---------------------------------------------------------------- launch
extern "C" void kernel_launch(void* const* d_in, const int* in_sizes, int n_in,
                              void* d_out, int out_size)
{
    const float* m_si    = (const float*)d_in[0];
    const float* ln_g    = (const float*)d_in[1];
    const float* ln_b    = (const float*)d_in[2];
    const float* w_ab    = (const float*)d_in[3];
    const float* w_final = (const float*)d_in[4];
    const float* b_final = (const float*)d_in[5];
    float* z = (float*)d_out;
    (void)in_sizes; (void)n_in; (void)out_size;

    ln_proj_kernel<<<1536, 256>>>(m_si, ln_g, ln_b, w_ab, w_final);

    cudaFuncSetAttribute(opm_mma_kernel,
                         cudaFuncAttributeMaxDynamicSharedMemorySize, SMEM2);
    dim3 grid(96, 96);   // (p-tiles, m-tiles), 128x128 each
    opm_mma_kernel<<<grid, 128, SMEM2>>>(b_final, z);
}

// round 14
// speedup vs baseline: 2.3539x; 1.1166x over previous
#include <cuda_runtime.h>
#include <cstdint>

#define S_DIM 384

// fp16 fragment-layout operand buffers (packed half2 words, written by kernel 1):
// g_Ah: [MI=m/16 (768)][kf2=k/16 (32)][128 w]  A-frag m16n8k16 (m=i*32+c, k=n)
// g_Bh: [NI=p/8 (1536)][kf2 (32)][64 w]        B-frag            (p=j*32+d)
// g_Wh: [zg=zz/16 (8)][kf2'=k'/16 (64)][128 w] A-frag for W, k' = c*32+d (= k identity)
__device__ unsigned int g_Ah[768 * 32 * 128];
__device__ unsigned int g_Bh[1536 * 32 * 64];
__device__ unsigned int g_Wh[8 * 64 * 128];

// ---------------------------------------------------------------- helpers
__device__ __forceinline__ uint32_t smem_u32(const void* p) {
    uint32_t a;
    asm("{ .reg .u64 t; cvta.to.shared.u64 t, %1; cvt.u32.u64 %0, t; }" : "=r"(a) : "l"(p));
    return a;
}
__device__ __forceinline__ uint32_t pack_h2(float lo, float hi) {
    uint32_t u;
    asm("cvt.rn.f16x2.f32 %0, %1, %2;" : "=r"(u) : "f"(hi), "f"(lo));
    return u;
}
__device__ __forceinline__ void lds128(uint32_t* v, uint32_t a) {
    asm volatile("ld.shared.v4.b32 {%0,%1,%2,%3}, [%4];"
                 : "=r"(v[0]), "=r"(v[1]), "=r"(v[2]), "=r"(v[3]) : "r"(a));
}
__device__ __forceinline__ void lds64(uint32_t* v, uint32_t a) {
    asm volatile("ld.shared.v2.b32 {%0,%1}, [%2];"
                 : "=r"(v[0]), "=r"(v[1]) : "r"(a));
}
__device__ __forceinline__ void sts32(uint32_t a, uint32_t v) {
    asm volatile("st.shared.b32 [%0], %1;" :: "r"(a), "r"(v) : "memory");
}
__device__ __forceinline__ void cp16(uint32_t dst, const void* src) {
    asm volatile("cp.async.cg.shared.global [%0], [%1], 16;" :: "r"(dst), "l"(src));
}
#define CP_COMMIT() asm volatile("cp.async.commit_group;" ::: "memory")
#define CP_WAIT2()  asm volatile("cp.async.wait_group 2;" ::: "memory")
#define CP_WAIT1()  asm volatile("cp.async.wait_group 1;" ::: "memory")
#define CP_WAIT0()  asm volatile("cp.async.wait_group 0;" ::: "memory")

// m16n8k16 fp16 MMA, f32 accum: D += A*B
__device__ __forceinline__ void mma16(float* d, const uint32_t* a, uint32_t b0, uint32_t b1) {
    asm volatile(
        "mma.sync.aligned.m16n8k16.row.col.f32.f16.f16.f32 "
        "{%0,%1,%2,%3}, {%4,%5,%6,%7}, {%8,%9}, {%0,%1,%2,%3};"
        : "+f"(d[0]), "+f"(d[1]), "+f"(d[2]), "+f"(d[3])
        : "r"(a[0]), "r"(a[1]), "r"(a[2]), "r"(a[3]), "r"(b0), "r"(b1));
}

// ---------------------------------------------------------------- kernel 1: LN + proj + W prep
// 3072 blocks: b -> (s = b>>3, n-slice of 64). W prep on blocks 0..255.
__global__ __launch_bounds__(256) void ln_proj_kernel(
    const float* __restrict__ m_si, const float* __restrict__ ln_g,
    const float* __restrict__ ln_b, const float* __restrict__ w_ab,
    const float* __restrict__ w_final)
{
    __shared__ float ws[64 * 33];
    __shared__ float a_s[32 * 66];
    __shared__ float b_s[32 * 66];

    int t = threadIdx.x, warp = t >> 5, lane = t & 31;
    int b = blockIdx.x;
    int s = b >> 3, n0 = (b & 7) * 64;

    if (b < 256) {   // W prep: g_Wh A-frag layout, k' = k (identity)
        int i = b * 256 + t;
        int zg = i >> 13, kf2 = (i >> 7) & 63, waddr = i & 127;
        int wl = waddr >> 2, wi = waddr & 3;
        int zz = zg * 16 + (wi & 1) * 8 + (wl >> 2);
        int k0 = kf2 * 16 + ((wi >> 1) & 1) * 8 + (wl & 3) * 2;
        g_Wh[i] = pack_h2(w_final[zz * 1024 + k0], w_final[zz * 1024 + k0 + 1]);
    }

    for (int idx = t; idx < 64 * 32; idx += 256)
        ws[(idx >> 5) * 33 + (idx & 31)] = w_ab[idx];
    __syncthreads();

    float g = ln_g[lane], bb = ln_b[lane];

    #pragma unroll
    for (int it = 0; it < 8; it++) {
        int nl = warp * 8 + it;                   // 0..63
        float x = m_si[((size_t)(s * 512 + n0 + nl)) * 32 + lane];

        float sum = x;
        #pragma unroll
        for (int o = 16; o; o >>= 1) sum += __shfl_xor_sync(0xFFFFFFFFu, sum, o);
        float mu = sum * (1.0f / 32.0f);
        float dx = x - mu;
        float v = dx * dx;
        #pragma unroll
        for (int o = 16; o; o >>= 1) v += __shfl_xor_sync(0xFFFFFFFFu, v, o);
        float mn = dx * rsqrtf(v * (1.0f / 32.0f) + 1e-5f) * g + bb;

        float aa = 0.0f, ab = 0.0f;
        #pragma unroll
        for (int c = 0; c < 32; c++) {
            float mc = __shfl_sync(0xFFFFFFFFu, mn, c);
            aa += mc * ws[lane * 33 + c];
            ab += mc * ws[(lane + 32) * 33 + c];
        }
        a_s[lane * 66 + nl] = aa;
        b_s[lane * 66 + nl] = ab;
    }
    __syncthreads();

    int kf0 = n0 >> 4;       // 4 kf2 per block

    // A gather: 1024 words [MIl 2][kf2l 4][waddr 128] -> 256 uint4 stores
    {
        int wb = t * 4;
        int MIl = wb >> 9, rem = wb & 511;
        int kf2l = rem >> 7, waddr = rem & 127;
        int wl = waddr >> 2;
        uint4 v;
        uint32_t* vp = &v.x;
        #pragma unroll
        for (int wi = 0; wi < 4; wi++) {
            int c  = MIl * 16 + (wi & 1) * 8 + (wl >> 2);
            int nl = kf2l * 16 + ((wi >> 1) & 1) * 8 + (wl & 3) * 2;
            vp[wi] = pack_h2(a_s[c * 66 + nl], a_s[c * 66 + nl + 1]);
        }
        *reinterpret_cast<uint4*>(
            g_Ah + ((size_t)(s * 2 + MIl) * 32 + kf0 + kf2l) * 128 + waddr) = v;
    }

    // B gather: 1024 words [NIl 4][kf2l 4][waddr 64] -> 256 uint4 stores
    {
        int wb = t * 4;
        int NIl = wb >> 8, rem = wb & 255;
        int kf2l = rem >> 6, waddr = rem & 63;
        uint4 v;
        uint32_t* vp = &v.x;
        #pragma unroll
        for (int e = 0; e < 4; e++) {
            int wd = waddr + e;
            int wl = wd >> 1, wi = wd & 1;
            int d_row = NIl * 8 + (wl >> 2);
            int nl = kf2l * 16 + wi * 8 + (wl & 3) * 2;
            vp[e] = pack_h2(b_s[d_row * 66 + nl], b_s[d_row * 66 + nl + 1]);
        }
        *reinterpret_cast<uint4*>(
            g_Bh + ((size_t)(s * 4 + NIl) * 32 + kf0 + kf2l) * 64 + waddr) = v;
    }
}

// ---------------------------------------------------------------- kernel 2
// 128 threads, 4 warps (2m x 2p), warp tile 64x64. CTA tile 128x128.
// Mainloop: 16 chunks of k=32, 4-stage ring x 16KB (A 8K + B 8K) = 65536.
// Epilogue reuse: osm o'-frags [kf2' 64][pf 2][272B] = 34816 at 0;
// per-warp W stage (2-buf of 4KB) at 34816 + w*8192 + buf*4096.
// SMEM2 = 67584 -> 3 CTAs/SM.
#define STG     16384u
#define OFF_WS  34816u
#define SMEM2   67584

__device__ __forceinline__ void load_AB(uint32_t slot, int ch, int mi0, int ni0, int t) {
    #pragma unroll
    for (int q = 0; q < 4; q++) {                 // A: 512 16B units
        int idx = t + q * 128;
        int MIi = idx >> 6, kf2l = (idx >> 5) & 1, unit = idx & 31;
        cp16(slot + (uint32_t)idx * 16u,
             g_Ah + ((size_t)(mi0 + MIi) * 32 + ch * 2 + kf2l) * 128 + unit * 4);
    }
    #pragma unroll
    for (int q = 0; q < 4; q++) {                 // B: 512 units
        int idx = t + q * 128;
        int NIl = idx >> 5, kf2l = (idx >> 4) & 1, unit = idx & 15;
        cp16(slot + 8192u + (uint32_t)idx * 16u,
             g_Bh + ((size_t)(ni0 + NIl) * 32 + ch * 2 + kf2l) * 64 + unit * 4);
    }
}

// W stage per chunk (k'=64): [zi 2][ks 4][512B] = 4KB per warp buffer; zi stride 2048B.
__device__ __forceinline__ void load_Wc(uint32_t sb, int ch, int buf, int w, int lane) {
    uint32_t wsb = sb + OFF_WS + (uint32_t)w * 8192u + (buf ? 4096u : 0u);
    #pragma unroll
    for (int q = 0; q < 8; q++) {
        int idx = lane + q * 32;                  // 0..255 16B units
        cp16(wsb + (uint32_t)idx * 16u,
             g_Wh + ((size_t)(2 * w + (idx >> 7)) * 64 + ch * 4 + ((idx >> 5) & 3)) * 128
                  + (idx & 31) * 4);
    }
}

__global__ __launch_bounds__(128, 3) void opm_mma_kernel(
    const float* __restrict__ b_final, float* __restrict__ z)
{
    extern __shared__ char smem_raw[];
    uint32_t sb = smem_u32(smem_raw);

    int t = threadIdx.x, w = t >> 5, lane = t & 31;
    int g = lane >> 2, r = lane & 3;
    int wm = w >> 1, wn = w & 1;                 // 2(m) x 2(p) warps, 64x64 tiles
    int mi0 = blockIdx.y * 8;
    int ni0 = blockIdx.x * 16;
    uint32_t l16 = (uint32_t)lane * 16u, l8 = (uint32_t)lane * 8u;

    float acc[4][8][4];
    #pragma unroll
    for (int i = 0; i < 4; i++)
        #pragma unroll
        for (int j = 0; j < 8; j++)
            #pragma unroll
            for (int cc = 0; cc < 4; cc++) acc[i][j][cc] = 0.0f;

    // ---- mainloop: 16 chunks of k=32 (2 kf2 steps), 4-stage ring
    load_AB(sb + 0u * STG, 0, mi0, ni0, t); CP_COMMIT();
    load_AB(sb + 1u * STG, 1, mi0, ni0, t); CP_COMMIT();
    load_AB(sb + 2u * STG, 2, mi0, ni0, t); CP_COMMIT();

    for (int s16 = 0; s16 < 16; s16++) {
        if (s16 <= 13) CP_WAIT2();
        else if (s16 == 14) CP_WAIT1();
        else CP_WAIT0();
        __syncthreads();

        uint32_t slot = sb + (uint32_t)(s16 & 3) * STG;

        #pragma unroll
        for (int ks = 0; ks < 2; ks++) {
            uint32_t bfr[8][2];
            #pragma unroll
            for (int j = 0; j < 8; j++)
                lds64(bfr[j], slot + 8192u
                              + (uint32_t)((wn * 8 + j) * 2 + ks) * 256u + l8);
            #pragma unroll
            for (int i = 0; i < 4; i++) {
                uint32_t a[4];
                lds128(a, slot + (uint32_t)((wm * 4 + i) * 2 + ks) * 512u + l16);
                #pragma unroll
                for (int j = 0; j < 8; j++)
                    mma16(acc[i][j], a, bfr[j][0], bfr[j][1]);
            }
        }

        if (s16 + 3 < 16) {
            load_AB(sb + (uint32_t)((s16 + 3) & 3) * STG, s16 + 3, mi0, ni0, t);
            CP_COMMIT();
        }
    }
    __syncthreads();

    // ---- prefetch W chunks 0,1 (per-warp 2-buf), spill o' (fp16 frags, 1/512)
    load_Wc(sb, 0, 0, w, lane); CP_COMMIT();
    load_Wc(sb, 1, 1, w, lane); CP_COMMIT();

    const float sc = 1.0f / 512.0f;
    #pragma unroll
    for (int i = 0; i < 4; i++)
        #pragma unroll
        for (int j = 0; j < 8; j++)
            #pragma unroll
            for (int ccp = 0; ccp < 2; ccp++) {
                int m = wm * 64 + i * 16 + g + ccp * 8;
                int p = wn * 64 + j * 8 + 2 * r;          // cc&1 is packed in half2
                int pair = ((m >> 5) << 2) | (p >> 5);
                int kf2p = (m & 31) * 2 + ((j >> 1) & 1);
                int lane_b = (pair & 7) * 4 + r;
                int addr = (kf2p * 2 + (pair >> 3)) * 272 + lane_b * 8 + (j & 1) * 4;
                sts32(sb + (uint32_t)addr,
                      pack_h2(acc[i][j][ccp * 2] * sc, acc[i][j][ccp * 2 + 1] * sc));
            }
    __syncthreads();

    // ---- epilogue: z[zz][pair] = W * o' (K=1024, 16 chunks of k'=64)
    float zacc[2][2][4];
    #pragma unroll
    for (int zi = 0; zi < 2; zi++)
        #pragma unroll
        for (int pf = 0; pf < 2; pf++)
            #pragma unroll
            for (int cc = 0; cc < 4; cc++) zacc[zi][pf][cc] = 0.0f;

    for (int ch = 0; ch < 16; ch++) {
        int buf = ch & 1;
        if (ch < 15) CP_WAIT1(); else CP_WAIT0();
        __syncwarp();

        uint32_t wsb = sb + OFF_WS + (uint32_t)w * 8192u + (buf ? 4096u : 0u);
        #pragma unroll
        for (int ks = 0; ks < 4; ks++) {
            uint32_t bfr[2][2];
            #pragma unroll
            for (int pf = 0; pf < 2; pf++)
                lds64(bfr[pf], sb + (uint32_t)(((ch * 4 + ks) * 2 + pf) * 272) + l8);
            #pragma unroll
            for (int zi = 0; zi < 2; zi++) {
                uint32_t aw[4];
                lds128(aw, wsb + (uint32_t)(zi * 2048 + ks * 512) + l16);
                #pragma unroll
                for (int pf = 0; pf < 2; pf++)
                    mma16(zacc[zi][pf], aw, bfr[pf][0], bfr[pf][1]);
            }
        }
        if (ch + 2 < 16) { load_Wc(sb, ch + 2, buf, w, lane); CP_COMMIT(); }
    }

    // ---- write z (+bias)
    float bf[2][2];
    #pragma unroll
    for (int zi = 0; zi < 2; zi++) {
        bf[zi][0] = b_final[w * 32 + zi * 16 + g];
        bf[zi][1] = b_final[w * 32 + zi * 16 + g + 8];
    }
    #pragma unroll
    for (int zi = 0; zi < 2; zi++)
        #pragma unroll
        for (int pf = 0; pf < 2; pf++)
            #pragma unroll
            for (int cc = 0; cc < 4; cc++) {
                int zz = w * 32 + zi * 16 + g + ((cc & 2) ? 8 : 0);
                int pr = pf * 8 + 2 * r + (cc & 1);
                int ig = blockIdx.y * 4 + (pr >> 2);
                int jg = blockIdx.x * 4 + (pr & 3);
                z[((size_t)(ig * S_DIM + jg)) * 128 + zz] =
                    zacc[zi][pf][cc] + bf[zi][(cc >> 1) & 1];
            }
}

// ---------------------------------------------------------------- launch
extern "C" void kernel_launch(void* const* d_in, const int* in_sizes, int n_in,
                              void* d_out, int out_size)
{
    const float* m_si    = (const float*)d_in[0];
    const float* ln_g    = (const float*)d_in[1];
    const float* ln_b    = (const float*)d_in[2];
    const float* w_ab    = (const float*)d_in[3];
    const float* w_final = (const float*)d_in[4];
    const float* b_final = (const float*)d_in[5];
    float* z = (float*)d_out;
    (void)in_sizes; (void)n_in; (void)out_size;

    ln_proj_kernel<<<3072, 256>>>(m_si, ln_g, ln_b, w_ab, w_final);

    cudaFuncSetAttribute(opm_mma_kernel,
                         cudaFuncAttributeMaxDynamicSharedMemorySize, SMEM2);
    dim3 grid(96, 96);   // (p-tiles, m-tiles), 128x128 each
    opm_mma_kernel<<<grid, 128, SMEM2>>>(b_final, z);
}

// round 15
// speedup vs baseline: 2.3913x; 1.0159x over previous
#include <cuda_runtime.h>
#include <cstdint>

#define S_DIM 384

// fp16 fragment-layout operand buffers (packed half2 words, written by kernel 1):
// g_Ah: [MI=m/16 (768)][kf2=k/16 (32)][128 w]  A-frag m16n8k16 (m=i*32+c, k=n)
// g_Bh: [NI=p/8 (1536)][kf2 (32)][64 w]        B-frag            (p=j*32+d)
// g_Wh: [zg=zz/16 (8)][kf2'=k'/16 (64)][128 w] A-frag for W, k' = c*32+d (= k identity)
__device__ unsigned int g_Ah[768 * 32 * 128];
__device__ unsigned int g_Bh[1536 * 32 * 64];
__device__ unsigned int g_Wh[8 * 64 * 128];

// ---------------------------------------------------------------- helpers
__device__ __forceinline__ uint32_t smem_u32(const void* p) {
    uint32_t a;
    asm("{ .reg .u64 t; cvta.to.shared.u64 t, %1; cvt.u32.u64 %0, t; }" : "=r"(a) : "l"(p));
    return a;
}
__device__ __forceinline__ uint32_t pack_h2(float lo, float hi) {
    uint32_t u;
    asm("cvt.rn.f16x2.f32 %0, %1, %2;" : "=r"(u) : "f"(hi), "f"(lo));
    return u;
}
__device__ __forceinline__ void lds128(uint32_t* v, uint32_t a) {
    asm volatile("ld.shared.v4.b32 {%0,%1,%2,%3}, [%4];"
                 : "=r"(v[0]), "=r"(v[1]), "=r"(v[2]), "=r"(v[3]) : "r"(a));
}
__device__ __forceinline__ void lds64(uint32_t* v, uint32_t a) {
    asm volatile("ld.shared.v2.b32 {%0,%1}, [%2];"
                 : "=r"(v[0]), "=r"(v[1]) : "r"(a));
}
__device__ __forceinline__ uint32_t lds32w(uint32_t a) {
    uint32_t v; asm volatile("ld.shared.b32 %0, [%1];" : "=r"(v) : "r"(a)); return v;
}
__device__ __forceinline__ void sts32(uint32_t a, uint32_t v) {
    asm volatile("st.shared.b32 [%0], %1;" :: "r"(a), "r"(v) : "memory");
}
__device__ __forceinline__ void sts32f(uint32_t a, float v) {
    asm volatile("st.shared.b32 [%0], %1;" :: "r"(a), "f"(v) : "memory");
}
__device__ __forceinline__ void sts16f(uint32_t a, float v) {
    asm volatile("{ .reg .b16 h; cvt.rn.f16.f32 h, %1; st.shared.b16 [%0], h; }"
                 :: "r"(a), "f"(v) : "memory");
}
__device__ __forceinline__ void cp16(uint32_t dst, const void* src) {
    asm volatile("cp.async.cg.shared.global [%0], [%1], 16;" :: "r"(dst), "l"(src));
}
#define CP_COMMIT() asm volatile("cp.async.commit_group;" ::: "memory")
#define CP_WAIT2()  asm volatile("cp.async.wait_group 2;" ::: "memory")
#define CP_WAIT1()  asm volatile("cp.async.wait_group 1;" ::: "memory")
#define CP_WAIT0()  asm volatile("cp.async.wait_group 0;" ::: "memory")

// m16n8k16 fp16 MMA, f32 accum: D += A*B
__device__ __forceinline__ void mma16(float* d, const uint32_t* a, uint32_t b0, uint32_t b1) {
    asm volatile(
        "mma.sync.aligned.m16n8k16.row.col.f32.f16.f16.f32 "
        "{%0,%1,%2,%3}, {%4,%5,%6,%7}, {%8,%9}, {%0,%1,%2,%3};"
        : "+f"(d[0]), "+f"(d[1]), "+f"(d[2]), "+f"(d[3])
        : "r"(a[0]), "r"(a[1]), "r"(a[2]), "r"(a[3]), "r"(b0), "r"(b1));
}

// ---------------------------------------------------------------- kernel 1: LN + tensor projection + W prep
// 3072 blocks: b -> (s = b>>3, n-slice of 64). W prep on blocks 0..255.
// Projection ab = W_ab * mn done via m16n8k16 mma (W_ab frags from global,
// mn staged in smem as fp16).
__global__ __launch_bounds__(256) void ln_proj_kernel(
    const float* __restrict__ m_si, const float* __restrict__ ln_g,
    const float* __restrict__ ln_b, const float* __restrict__ w_ab,
    const float* __restrict__ w_final)
{
    __shared__ unsigned short mn_s[64 * 36];   // [row][36 halves], stride 18 words
    __shared__ float a_s[32 * 66];
    __shared__ float b_s[32 * 66];

    int t = threadIdx.x, warp = t >> 5, lane = t & 31;
    int g = lane >> 2, r = lane & 3;
    int b = blockIdx.x;
    int s = b >> 3, n0 = (b & 7) * 64;

    if (b < 256) {   // W prep: g_Wh A-frag layout, k' = k (identity)
        int i = b * 256 + t;
        int zg = i >> 13, kf2 = (i >> 7) & 63, waddr = i & 127;
        int wl = waddr >> 2, wi = waddr & 3;
        int zz = zg * 16 + (wi & 1) * 8 + (wl >> 2);
        int k0 = kf2 * 16 + ((wi >> 1) & 1) * 8 + (wl & 3) * 2;
        g_Wh[i] = pack_h2(w_final[zz * 1024 + k0], w_final[zz * 1024 + k0 + 1]);
    }

    // ---- W_ab A-fragments (each warp loads the full 64x32, fp16 packed)
    // frag (mi, ki, wi): d = mi*16 + (wi&1)*8 + g ; k = ki*16 + ((wi>>1)&1)*8 + 2r
    uint32_t awf[4][2][4];
    #pragma unroll
    for (int mi = 0; mi < 4; mi++)
        #pragma unroll
        for (int ki = 0; ki < 2; ki++)
            #pragma unroll
            for (int wi = 0; wi < 4; wi++) {
                int d = mi * 16 + (wi & 1) * 8 + g;
                int k = ki * 16 + ((wi >> 1) & 1) * 8 + 2 * r;
                float2 wv = *reinterpret_cast<const float2*>(w_ab + d * 32 + k);
                awf[mi][ki][wi] = pack_h2(wv.x, wv.y);
            }

    // ---- LayerNorm: warp handles rows nl = warp*8 .. +7; lane = channel c
    uint32_t mnb = smem_u32(mn_s);
    float gg = ln_g[lane], bb = ln_b[lane];

    #pragma unroll
    for (int it = 0; it < 8; it++) {
        int nl = warp * 8 + it;
        float x = m_si[((size_t)(s * 512 + n0 + nl)) * 32 + lane];

        float sum = x;
        #pragma unroll
        for (int o = 16; o; o >>= 1) sum += __shfl_xor_sync(0xFFFFFFFFu, sum, o);
        float mu = sum * (1.0f / 32.0f);
        float dx = x - mu;
        float v = dx * dx;
        #pragma unroll
        for (int o = 16; o; o >>= 1) v += __shfl_xor_sync(0xFFFFFFFFu, v, o);
        float mn = dx * rsqrtf(v * (1.0f / 32.0f) + 1e-5f) * gg + bb;

        sts16f(mnb + (uint32_t)(nl * 36 + lane) * 2u, mn);
    }
    __syncwarp();

    // ---- projection mma: D[64 d][8 rows] for this warp's rows
    float acc[4][4];
    #pragma unroll
    for (int mi = 0; mi < 4; mi++)
        #pragma unroll
        for (int cc = 0; cc < 4; cc++) acc[mi][cc] = 0.0f;

    #pragma unroll
    for (int ki = 0; ki < 2; ki++) {
        // B-frag: n(row) = warp*8 + g ; b0: k = ki*16 + 2r, b1: k = ki*16 + 8 + 2r
        uint32_t rowb = mnb + (uint32_t)((warp * 8 + g) * 18 + ki * 8 + r) * 4u;
        uint32_t b0 = lds32w(rowb);
        uint32_t b1 = lds32w(rowb + 16u);
        #pragma unroll
        for (int mi = 0; mi < 4; mi++)
            mma16(acc[mi], awf[mi][ki], b0, b1);
    }

    // ---- scatter acc -> a_s / b_s (fp32): d = mi*16 + (cc&2?8:0) + g,
    //      nl = warp*8 + 2r + (cc&1)
    uint32_t asb = smem_u32(a_s), bsb = smem_u32(b_s);
    #pragma unroll
    for (int mi = 0; mi < 4; mi++)
        #pragma unroll
        for (int cc = 0; cc < 4; cc++) {
            int d = mi * 16 + ((cc & 2) ? 8 : 0) + g;
            int nl = warp * 8 + 2 * r + (cc & 1);
            uint32_t base = (d < 32) ? asb : bsb;
            sts32f(base + (uint32_t)((d & 31) * 66 + nl) * 4u, acc[mi][cc]);
        }
    __syncthreads();

    int kf0 = n0 >> 4;       // 4 kf2 per block

    // A gather: 1024 words [MIl 2][kf2l 4][waddr 128] -> 256 uint4 stores
    {
        int wb = t * 4;
        int MIl = wb >> 9, rem = wb & 511;
        int kf2l = rem >> 7, waddr = rem & 127;
        int wl = waddr >> 2;
        uint4 v;
        uint32_t* vp = &v.x;
        #pragma unroll
        for (int wi = 0; wi < 4; wi++) {
            int c  = MIl * 16 + (wi & 1) * 8 + (wl >> 2);
            int nl = kf2l * 16 + ((wi >> 1) & 1) * 8 + (wl & 3) * 2;
            vp[wi] = pack_h2(a_s[c * 66 + nl], a_s[c * 66 + nl + 1]);
        }
        *reinterpret_cast<uint4*>(
            g_Ah + ((size_t)(s * 2 + MIl) * 32 + kf0 + kf2l) * 128 + waddr) = v;
    }

    // B gather: 1024 words [NIl 4][kf2l 4][waddr 64] -> 256 uint4 stores
    {
        int wb = t * 4;
        int NIl = wb >> 8, rem = wb & 255;
        int kf2l = rem >> 6, waddr = rem & 63;
        uint4 v;
        uint32_t* vp = &v.x;
        #pragma unroll
        for (int e = 0; e < 4; e++) {
            int wd = waddr + e;
            int wl = wd >> 1, wi = wd & 1;
            int d_row = NIl * 8 + (wl >> 2);
            int nl = kf2l * 16 + wi * 8 + (wl & 3) * 2;
            vp[e] = pack_h2(b_s[d_row * 66 + nl], b_s[d_row * 66 + nl + 1]);
        }
        *reinterpret_cast<uint4*>(
            g_Bh + ((size_t)(s * 4 + NIl) * 32 + kf0 + kf2l) * 64 + waddr) = v;
    }
}

// ---------------------------------------------------------------- kernel 2 (R14, unchanged)
// 128 threads, 4 warps (2m x 2p), warp tile 64x64. CTA tile 128x128.
// Mainloop: 16 chunks of k=32, 4-stage ring x 16KB = 65536.
// Epilogue reuse: osm o'-frags [kf2' 64][pf 2][272B] = 34816 at 0;
// per-warp W stage (2-buf of 4KB) at 34816 + w*8192 + buf*4096.
// SMEM2 = 67584 -> 3 CTAs/SM.
#define STG     16384u
#define OFF_WS  34816u
#define SMEM2   67584

__device__ __forceinline__ void load_AB(uint32_t slot, int ch, int mi0, int ni0, int t) {
    #pragma unroll
    for (int q = 0; q < 4; q++) {                 // A: 512 16B units
        int idx = t + q * 128;
        int MIi = idx >> 6, kf2l = (idx >> 5) & 1, unit = idx & 31;
        cp16(slot + (uint32_t)idx * 16u,
             g_Ah + ((size_t)(mi0 + MIi) * 32 + ch * 2 + kf2l) * 128 + unit * 4);
    }
    #pragma unroll
    for (int q = 0; q < 4; q++) {                 // B: 512 units
        int idx = t + q * 128;
        int NIl = idx >> 5, kf2l = (idx >> 4) & 1, unit = idx & 15;
        cp16(slot + 8192u + (uint32_t)idx * 16u,
             g_Bh + ((size_t)(ni0 + NIl) * 32 + ch * 2 + kf2l) * 64 + unit * 4);
    }
}

// W stage per chunk (k'=64): [zi 2][ks 4][512B] = 4KB per warp buffer; zi stride 2048B.
__device__ __forceinline__ void load_Wc(uint32_t sb, int ch, int buf, int w, int lane) {
    uint32_t wsb = sb + OFF_WS + (uint32_t)w * 8192u + (buf ? 4096u : 0u);
    #pragma unroll
    for (int q = 0; q < 8; q++) {
        int idx = lane + q * 32;                  // 0..255 16B units
        cp16(wsb + (uint32_t)idx * 16u,
             g_Wh + ((size_t)(2 * w + (idx >> 7)) * 64 + ch * 4 + ((idx >> 5) & 3)) * 128
                  + (idx & 31) * 4);
    }
}

__global__ __launch_bounds__(128, 3) void opm_mma_kernel(
    const float* __restrict__ b_final, float* __restrict__ z)
{
    extern __shared__ char smem_raw[];
    uint32_t sb = smem_u32(smem_raw);

    int t = threadIdx.x, w = t >> 5, lane = t & 31;
    int g = lane >> 2, r = lane & 3;
    int wm = w >> 1, wn = w & 1;                 // 2(m) x 2(p) warps, 64x64 tiles
    int mi0 = blockIdx.y * 8;
    int ni0 = blockIdx.x * 16;
    uint32_t l16 = (uint32_t)lane * 16u, l8 = (uint32_t)lane * 8u;

    float acc[4][8][4];
    #pragma unroll
    for (int i = 0; i < 4; i++)
        #pragma unroll
        for (int j = 0; j < 8; j++)
            #pragma unroll
            for (int cc = 0; cc < 4; cc++) acc[i][j][cc] = 0.0f;

    // ---- mainloop: 16 chunks of k=32 (2 kf2 steps), 4-stage ring
    load_AB(sb + 0u * STG, 0, mi0, ni0, t); CP_COMMIT();
    load_AB(sb + 1u * STG, 1, mi0, ni0, t); CP_COMMIT();
    load_AB(sb + 2u * STG, 2, mi0, ni0, t); CP_COMMIT();

    for (int s16 = 0; s16 < 16; s16++) {
        if (s16 <= 13) CP_WAIT2();
        else if (s16 == 14) CP_WAIT1();
        else CP_WAIT0();
        __syncthreads();

        uint32_t slot = sb + (uint32_t)(s16 & 3) * STG;

        #pragma unroll
        for (int ks = 0; ks < 2; ks++) {
            uint32_t bfr[8][2];
            #pragma unroll
            for (int j = 0; j < 8; j++)
                lds64(bfr[j], slot + 8192u
                              + (uint32_t)((wn * 8 + j) * 2 + ks) * 256u + l8);
            #pragma unroll
            for (int i = 0; i < 4; i++) {
                uint32_t a[4];
                lds128(a, slot + (uint32_t)((wm * 4 + i) * 2 + ks) * 512u + l16);
                #pragma unroll
                for (int j = 0; j < 8; j++)
                    mma16(acc[i][j], a, bfr[j][0], bfr[j][1]);
            }
        }

        if (s16 + 3 < 16) {
            load_AB(sb + (uint32_t)((s16 + 3) & 3) * STG, s16 + 3, mi0, ni0, t);
            CP_COMMIT();
        }
    }
    __syncthreads();

    // ---- prefetch W chunks 0,1 (per-warp 2-buf), spill o' (fp16 frags, 1/512)
    load_Wc(sb, 0, 0, w, lane); CP_COMMIT();
    load_Wc(sb, 1, 1, w, lane); CP_COMMIT();

    const float sc = 1.0f / 512.0f;
    #pragma unroll
    for (int i = 0; i < 4; i++)
        #pragma unroll
        for (int j = 0; j < 8; j++)
            #pragma unroll
            for (int ccp = 0; ccp < 2; ccp++) {
                int m = wm * 64 + i * 16 + g + ccp * 8;
                int p = wn * 64 + j * 8 + 2 * r;          // cc&1 is packed in half2
                int pair = ((m >> 5) << 2) | (p >> 5);
                int kf2p = (m & 31) * 2 + ((j >> 1) & 1);
                int lane_b = (pair & 7) * 4 + r;
                int addr = (kf2p * 2 + (pair >> 3)) * 272 + lane_b * 8 + (j & 1) * 4;
                sts32(sb + (uint32_t)addr,
                      pack_h2(acc[i][j][ccp * 2] * sc, acc[i][j][ccp * 2 + 1] * sc));
            }
    __syncthreads();

    // ---- epilogue: z[zz][pair] = W * o' (K=1024, 16 chunks of k'=64)
    float zacc[2][2][4];
    #pragma unroll
    for (int zi = 0; zi < 2; zi++)
        #pragma unroll
        for (int pf = 0; pf < 2; pf++)
            #pragma unroll
            for (int cc = 0; cc < 4; cc++) zacc[zi][pf][cc] = 0.0f;

    for (int ch = 0; ch < 16; ch++) {
        int buf = ch & 1;
        if (ch < 15) CP_WAIT1(); else CP_WAIT0();
        __syncwarp();

        uint32_t wsb = sb + OFF_WS + (uint32_t)w * 8192u + (buf ? 4096u : 0u);
        #pragma unroll
        for (int ks = 0; ks < 4; ks++) {
            uint32_t bfr[2][2];
            #pragma unroll
            for (int pf = 0; pf < 2; pf++)
                lds64(bfr[pf], sb + (uint32_t)(((ch * 4 + ks) * 2 + pf) * 272) + l8);
            #pragma unroll
            for (int zi = 0; zi < 2; zi++) {
                uint32_t aw[4];
                lds128(aw, wsb + (uint32_t)(zi * 2048 + ks * 512) + l16);
                #pragma unroll
                for (int pf = 0; pf < 2; pf++)
                    mma16(zacc[zi][pf], aw, bfr[pf][0], bfr[pf][1]);
            }
        }
        if (ch + 2 < 16) { load_Wc(sb, ch + 2, buf, w, lane); CP_COMMIT(); }
    }

    // ---- write z (+bias)
    float bf[2][2];
    #pragma unroll
    for (int zi = 0; zi < 2; zi++) {
        bf[zi][0] = b_final[w * 32 + zi * 16 + g];
        bf[zi][1] = b_final[w * 32 + zi * 16 + g + 8];
    }
    #pragma unroll
    for (int zi = 0; zi < 2; zi++)
        #pragma unroll
        for (int pf = 0; pf < 2; pf++)
            #pragma unroll
            for (int cc = 0; cc < 4; cc++) {
                int zz = w * 32 + zi * 16 + g + ((cc & 2) ? 8 : 0);
                int pr = pf * 8 + 2 * r + (cc & 1);
                int ig = blockIdx.y * 4 + (pr >> 2);
                int jg = blockIdx.x * 4 + (pr & 3);
                z[((size_t)(ig * S_DIM + jg)) * 128 + zz] =
                    zacc[zi][pf][cc] + bf[zi][(cc >> 1) & 1];
            }
}

// ---------------------------------------------------------------- launch
extern "C" void kernel_launch(void* const* d_in, const int* in_sizes, int n_in,
                              void* d_out, int out_size)
{
    const float* m_si    = (const float*)d_in[0];
    const float* ln_g    = (const float*)d_in[1];
    const float* ln_b    = (const float*)d_in[2];
    const float* w_ab    = (const float*)d_in[3];
    const float* w_final = (const float*)d_in[4];
    const float* b_final = (const float*)d_in[5];
    float* z = (float*)d_out;
    (void)in_sizes; (void)n_in; (void)out_size;

    ln_proj_kernel<<<3072, 256>>>(m_si, ln_g, ln_b, w_ab, w_final);

    cudaFuncSetAttribute(opm_mma_kernel,
                         cudaFuncAttributeMaxDynamicSharedMemorySize, SMEM2);
    dim3 grid(96, 96);   // (p-tiles, m-tiles), 128x128 each
    opm_mma_kernel<<<grid, 128, SMEM2>>>(b_final, z);
}

// round 16
// speedup vs baseline: 2.5849x; 1.0810x over previous
#include <cuda_runtime.h>
#include <cstdint>

#define S_DIM 384

// fp16 fragment-layout operand buffers (packed half2 words, written by kernel 1):
// g_Ah: [MI=m/16 (768)][kf2=k/16 (32)][128 w]  A-frag m16n8k16 (m=i*32+c, k=n)
// g_Bh: [NI=p/8 (1536)][kf2 (32)][64 w]        B-frag            (p=j*32+d)
// g_Wh: [zg=zz/16 (8)][kf2'=k'/16 (64)][128 w] A-frag for W, k' = c*32+d (= k identity)
__device__ unsigned int g_Ah[768 * 32 * 128];
__device__ unsigned int g_Bh[1536 * 32 * 64];
__device__ unsigned int g_Wh[8 * 64 * 128];

// ---------------------------------------------------------------- helpers
__device__ __forceinline__ uint32_t smem_u32(const void* p) {
    uint32_t a;
    asm("{ .reg .u64 t; cvta.to.shared.u64 t, %1; cvt.u32.u64 %0, t; }" : "=r"(a) : "l"(p));
    return a;
}
__device__ __forceinline__ uint32_t pack_h2(float lo, float hi) {
    uint32_t u;
    asm("cvt.rn.f16x2.f32 %0, %1, %2;" : "=r"(u) : "f"(hi), "f"(lo));
    return u;
}
__device__ __forceinline__ void lds128(uint32_t* v, uint32_t a) {
    asm volatile("ld.shared.v4.b32 {%0,%1,%2,%3}, [%4];"
                 : "=r"(v[0]), "=r"(v[1]), "=r"(v[2]), "=r"(v[3]) : "r"(a));
}
__device__ __forceinline__ void lds64(uint32_t* v, uint32_t a) {
    asm volatile("ld.shared.v2.b32 {%0,%1}, [%2];"
                 : "=r"(v[0]), "=r"(v[1]) : "r"(a));
}
__device__ __forceinline__ uint32_t lds32w(uint32_t a) {
    uint32_t v; asm volatile("ld.shared.b32 %0, [%1];" : "=r"(v) : "r"(a)); return v;
}
__device__ __forceinline__ void sts32(uint32_t a, uint32_t v) {
    asm volatile("st.shared.b32 [%0], %1;" :: "r"(a), "r"(v) : "memory");
}
__device__ __forceinline__ void sts32f(uint32_t a, float v) {
    asm volatile("st.shared.b32 [%0], %1;" :: "r"(a), "f"(v) : "memory");
}
__device__ __forceinline__ void sts16f(uint32_t a, float v) {
    asm volatile("{ .reg .b16 h; cvt.rn.f16.f32 h, %1; st.shared.b16 [%0], h; }"
                 :: "r"(a), "f"(v) : "memory");
}
__device__ __forceinline__ void cp16(uint32_t dst, const void* src) {
    asm volatile("cp.async.cg.shared.global [%0], [%1], 16;" :: "r"(dst), "l"(src));
}
#define CP_COMMIT() asm volatile("cp.async.commit_group;" ::: "memory")
#define CP_WAIT2()  asm volatile("cp.async.wait_group 2;" ::: "memory")
#define CP_WAIT1()  asm volatile("cp.async.wait_group 1;" ::: "memory")
#define CP_WAIT0()  asm volatile("cp.async.wait_group 0;" ::: "memory")

// m16n8k16 fp16 MMA, f32 accum: D += A*B
__device__ __forceinline__ void mma16(float* d, const uint32_t* a, uint32_t b0, uint32_t b1) {
    asm volatile(
        "mma.sync.aligned.m16n8k16.row.col.f32.f16.f16.f32 "
        "{%0,%1,%2,%3}, {%4,%5,%6,%7}, {%8,%9}, {%0,%1,%2,%3};"
        : "+f"(d[0]), "+f"(d[1]), "+f"(d[2]), "+f"(d[3])
        : "r"(a[0]), "r"(a[1]), "r"(a[2]), "r"(a[3]), "r"(b0), "r"(b1));
}

// ---------------------------------------------------------------- kernel 1 (R15, unchanged)
__global__ __launch_bounds__(256) void ln_proj_kernel(
    const float* __restrict__ m_si, const float* __restrict__ ln_g,
    const float* __restrict__ ln_b, const float* __restrict__ w_ab,
    const float* __restrict__ w_final)
{
    __shared__ unsigned short mn_s[64 * 36];
    __shared__ float a_s[32 * 66];
    __shared__ float b_s[32 * 66];

    int t = threadIdx.x, warp = t >> 5, lane = t & 31;
    int g = lane >> 2, r = lane & 3;
    int b = blockIdx.x;
    int s = b >> 3, n0 = (b & 7) * 64;

    if (b < 256) {
        int i = b * 256 + t;
        int zg = i >> 13, kf2 = (i >> 7) & 63, waddr = i & 127;
        int wl = waddr >> 2, wi = waddr & 3;
        int zz = zg * 16 + (wi & 1) * 8 + (wl >> 2);
        int k0 = kf2 * 16 + ((wi >> 1) & 1) * 8 + (wl & 3) * 2;
        g_Wh[i] = pack_h2(w_final[zz * 1024 + k0], w_final[zz * 1024 + k0 + 1]);
    }

    uint32_t awf[4][2][4];
    #pragma unroll
    for (int mi = 0; mi < 4; mi++)
        #pragma unroll
        for (int ki = 0; ki < 2; ki++)
            #pragma unroll
            for (int wi = 0; wi < 4; wi++) {
                int d = mi * 16 + (wi & 1) * 8 + g;
                int k = ki * 16 + ((wi >> 1) & 1) * 8 + 2 * r;
                float2 wv = *reinterpret_cast<const float2*>(w_ab + d * 32 + k);
                awf[mi][ki][wi] = pack_h2(wv.x, wv.y);
            }

    uint32_t mnb = smem_u32(mn_s);
    float gg = ln_g[lane], bb = ln_b[lane];

    #pragma unroll
    for (int it = 0; it < 8; it++) {
        int nl = warp * 8 + it;
        float x = m_si[((size_t)(s * 512 + n0 + nl)) * 32 + lane];
        float sum = x;
        #pragma unroll
        for (int o = 16; o; o >>= 1) sum += __shfl_xor_sync(0xFFFFFFFFu, sum, o);
        float mu = sum * (1.0f / 32.0f);
        float dx = x - mu;
        float v = dx * dx;
        #pragma unroll
        for (int o = 16; o; o >>= 1) v += __shfl_xor_sync(0xFFFFFFFFu, v, o);
        float mn = dx * rsqrtf(v * (1.0f / 32.0f) + 1e-5f) * gg + bb;
        sts16f(mnb + (uint32_t)(nl * 36 + lane) * 2u, mn);
    }
    __syncwarp();

    float acc[4][4];
    #pragma unroll
    for (int mi = 0; mi < 4; mi++)
        #pragma unroll
        for (int cc = 0; cc < 4; cc++) acc[mi][cc] = 0.0f;

    #pragma unroll
    for (int ki = 0; ki < 2; ki++) {
        uint32_t rowb = mnb + (uint32_t)((warp * 8 + g) * 18 + ki * 8 + r) * 4u;
        uint32_t b0 = lds32w(rowb);
        uint32_t b1 = lds32w(rowb + 16u);
        #pragma unroll
        for (int mi = 0; mi < 4; mi++)
            mma16(acc[mi], awf[mi][ki], b0, b1);
    }

    uint32_t asb = smem_u32(a_s), bsb = smem_u32(b_s);
    #pragma unroll
    for (int mi = 0; mi < 4; mi++)
        #pragma unroll
        for (int cc = 0; cc < 4; cc++) {
            int d = mi * 16 + ((cc & 2) ? 8 : 0) + g;
            int nl = warp * 8 + 2 * r + (cc & 1);
            uint32_t base = (d < 32) ? asb : bsb;
            sts32f(base + (uint32_t)((d & 31) * 66 + nl) * 4u, acc[mi][cc]);
        }
    __syncthreads();

    int kf0 = n0 >> 4;

    {
        int wb = t * 4;
        int MIl = wb >> 9, rem = wb & 511;
        int kf2l = rem >> 7, waddr = rem & 127;
        int wl = waddr >> 2;
        uint4 v;
        uint32_t* vp = &v.x;
        #pragma unroll
        for (int wi = 0; wi < 4; wi++) {
            int c  = MIl * 16 + (wi & 1) * 8 + (wl >> 2);
            int nl = kf2l * 16 + ((wi >> 1) & 1) * 8 + (wl & 3) * 2;
            vp[wi] = pack_h2(a_s[c * 66 + nl], a_s[c * 66 + nl + 1]);
        }
        *reinterpret_cast<uint4*>(
            g_Ah + ((size_t)(s * 2 + MIl) * 32 + kf0 + kf2l) * 128 + waddr) = v;
    }
    {
        int wb = t * 4;
        int NIl = wb >> 8, rem = wb & 255;
        int kf2l = rem >> 6, waddr = rem & 63;
        uint4 v;
        uint32_t* vp = &v.x;
        #pragma unroll
        for (int e = 0; e < 4; e++) {
            int wd = waddr + e;
            int wl = wd >> 1, wi = wd & 1;
            int d_row = NIl * 8 + (wl >> 2);
            int nl = kf2l * 16 + wi * 8 + (wl & 3) * 2;
            vp[e] = pack_h2(b_s[d_row * 66 + nl], b_s[d_row * 66 + nl + 1]);
        }
        *reinterpret_cast<uint4*>(
            g_Bh + ((size_t)(s * 4 + NIl) * 32 + kf0 + kf2l) * 64 + waddr) = v;
    }
}

// ---------------------------------------------------------------- kernel 2
// 128 threads, 4 warps (2m x 2p), warp tile 64x64. CTA: 128(m) x 256(p) via
// TWO sequential 128x128 phases sharing one W-epilogue (32 pairs).
// SMEM: osm [rows 256][264B] = 67584 at 0 (row = kf2' + i*64, i=pf).
//   Mainloop stages: 4 x 8KB at 67584 (k=16 chunks).  W stage (epilogue):
//   same region, per-warp 2-buf of 4KB at 67584 + w*8192 + buf*4096.
// SMEM2 = 100352 -> 2 CTAs/SM.
#define OFF_ST  67584u
#define STG     8192u
#define SMEM2   100352

__device__ __forceinline__ void load_AB(uint32_t slot, int ch, int mi0, int ni0, int t) {
    #pragma unroll
    for (int q = 0; q < 2; q++) {                 // A: 256 16B units [MIi 8][unit 32]
        int idx = t + q * 128;
        cp16(slot + (uint32_t)idx * 16u,
             g_Ah + ((size_t)(mi0 + (idx >> 5)) * 32 + ch) * 128 + (idx & 31) * 4);
    }
    #pragma unroll
    for (int q = 0; q < 2; q++) {                 // B: 256 units [NIl 16][unit 16]
        int idx = t + q * 128;
        cp16(slot + 4096u + (uint32_t)idx * 16u,
             g_Bh + ((size_t)(ni0 + (idx >> 4)) * 32 + ch) * 64 + (idx & 15) * 4);
    }
}

// W stage per chunk (k'=64): [zi 2][ks 4][512B] = 4KB per warp buffer.
__device__ __forceinline__ void load_Wc(uint32_t sb, int ch, int buf, int w, int lane) {
    uint32_t wsb = sb + OFF_ST + (uint32_t)w * 8192u + (buf ? 4096u : 0u);
    #pragma unroll
    for (int q = 0; q < 8; q++) {
        int idx = lane + q * 32;
        cp16(wsb + (uint32_t)idx * 16u,
             g_Wh + ((size_t)(2 * w + (idx >> 7)) * 64 + ch * 4 + ((idx >> 5) & 3)) * 128
                  + (idx & 31) * 4);
    }
}

__global__ __launch_bounds__(128, 2) void opm_mma_kernel(
    const float* __restrict__ b_final, float* __restrict__ z)
{
    extern __shared__ char smem_raw[];
    uint32_t sb = smem_u32(smem_raw);

    int t = threadIdx.x, w = t >> 5, lane = t & 31;
    int g = lane >> 2, r = lane & 3;
    int wm = w >> 1, wn = w & 1;                 // 2(m) x 2(p) warps, 64x64 tiles
    int mi0 = blockIdx.y * 8;
    int nib = blockIdx.x * 32;                   // NI base (8 j per CTA)
    uint32_t l16 = (uint32_t)lane * 16u, l8 = (uint32_t)lane * 8u;

    // initial preload: phase-0 chunks 0..2
    load_AB(sb + OFF_ST + 0u * STG, 0, mi0, nib, t); CP_COMMIT();
    load_AB(sb + OFF_ST + 1u * STG, 1, mi0, nib, t); CP_COMMIT();
    load_AB(sb + OFF_ST + 2u * STG, 2, mi0, nib, t); CP_COMMIT();

    const float sc = 1.0f / 512.0f;

    #pragma unroll 1
    for (int ph = 0; ph < 2; ph++) {
        int ni0 = nib + ph * 16;

        float acc[4][8][4];
        #pragma unroll
        for (int i = 0; i < 4; i++)
            #pragma unroll
            for (int j = 0; j < 8; j++)
                #pragma unroll
                for (int cc = 0; cc < 4; cc++) acc[i][j][cc] = 0.0f;

        // ---- mainloop: 32 chunks of k=16, 4-stage ring
        for (int s = 0; s < 32; s++) {
            if (s <= 29) CP_WAIT2();
            else if (s == 30) CP_WAIT1();
            else CP_WAIT0();
            __syncthreads();

            uint32_t slot = sb + OFF_ST + (uint32_t)(s & 3) * STG;

            uint32_t bfr[8][2];
            #pragma unroll
            for (int j = 0; j < 8; j++)
                lds64(bfr[j], slot + 4096u + (uint32_t)(wn * 8 + j) * 256u + l8);
            #pragma unroll
            for (int i = 0; i < 4; i++) {
                uint32_t a[4];
                lds128(a, slot + (uint32_t)(wm * 4 + i) * 512u + l16);
                #pragma unroll
                for (int j = 0; j < 8; j++)
                    mma16(acc[i][j], a, bfr[j][0], bfr[j][1]);
            }

            if (s + 3 < 32) {
                load_AB(sb + OFF_ST + (uint32_t)((s + 3) & 3) * STG, s + 3, mi0, ni0, t);
                CP_COMMIT();
            }
        }
        __syncthreads();

        // prefetch next phase / epilogue W while spilling
        if (ph == 0) {
            load_AB(sb + OFF_ST + 0u * STG, 0, mi0, nib + 16, t); CP_COMMIT();
            load_AB(sb + OFF_ST + 1u * STG, 1, mi0, nib + 16, t); CP_COMMIT();
            load_AB(sb + OFF_ST + 2u * STG, 2, mi0, nib + 16, t); CP_COMMIT();
        } else {
            load_Wc(sb, 0, 0, w, lane); CP_COMMIT();
            load_Wc(sb, 1, 1, w, lane); CP_COMMIT();
        }

        // ---- spill o' (fp16 frags, 1/512 folded): row = kf2' + i*64, 264B rows
        #pragma unroll
        for (int i = 0; i < 4; i++)
            #pragma unroll
            for (int j = 0; j < 8; j++)
                #pragma unroll
                for (int ccp = 0; ccp < 2; ccp++) {
                    int m = wm * 64 + i * 16 + g + ccp * 8;
                    int j8 = ph * 4 + wn * 2 + (j >> 2);          // pair & 7
                    int kf2p = (m & 31) * 2 + ((j >> 1) & 1);
                    int row = kf2p + (m >> 5) * 64;
                    int addr = row * 264 + (j8 * 4 + r) * 8 + (j & 1) * 4;
                    sts32(sb + (uint32_t)addr,
                          pack_h2(acc[i][j][ccp * 2] * sc, acc[i][j][ccp * 2 + 1] * sc));
                }
        __syncthreads();
    }

    // ---- epilogue: z[zz][pair] = W * o' (K=1024, 16 chunks of k'=64, 32 pairs)
    float zacc[2][4][4];
    #pragma unroll
    for (int zi = 0; zi < 2; zi++)
        #pragma unroll
        for (int pf = 0; pf < 4; pf++)
            #pragma unroll
            for (int cc = 0; cc < 4; cc++) zacc[zi][pf][cc] = 0.0f;

    for (int ch = 0; ch < 16; ch++) {
        int buf = ch & 1;
        if (ch < 15) CP_WAIT1(); else CP_WAIT0();
        __syncwarp();

        uint32_t wsb = sb + OFF_ST + (uint32_t)w * 8192u + (buf ? 4096u : 0u);
        #pragma unroll
        for (int ks = 0; ks < 4; ks++) {
            uint32_t bfr[4][2];
            #pragma unroll
            for (int pf = 0; pf < 4; pf++)
                lds64(bfr[pf], sb + (uint32_t)(((ch * 4 + ks) + pf * 64) * 264) + l8);
            #pragma unroll
            for (int zi = 0; zi < 2; zi++) {
                uint32_t aw[4];
                lds128(aw, wsb + (uint32_t)(zi * 2048 + ks * 512) + l16);
                #pragma unroll
                for (int pf = 0; pf < 4; pf++)
                    mma16(zacc[zi][pf], aw, bfr[pf][0], bfr[pf][1]);
            }
        }
        if (ch + 2 < 16) { load_Wc(sb, ch + 2, buf, w, lane); CP_COMMIT(); }
    }

    // ---- write z (+bias): pair = pf*8 + (2r + (cc&1)); ig = by*4+pf, jg = bx*8+j8
    float bf[2][2];
    #pragma unroll
    for (int zi = 0; zi < 2; zi++) {
        bf[zi][0] = b_final[w * 32 + zi * 16 + g];
        bf[zi][1] = b_final[w * 32 + zi * 16 + g + 8];
    }
    #pragma unroll
    for (int zi = 0; zi < 2; zi++)
        #pragma unroll
        for (int pf = 0; pf < 4; pf++)
            #pragma unroll
            for (int cc = 0; cc < 4; cc++) {
                int zz = w * 32 + zi * 16 + g + ((cc & 2) ? 8 : 0);
                int jg = blockIdx.x * 8 + 2 * r + (cc & 1);
                int ig = blockIdx.y * 4 + pf;
                z[((size_t)(ig * S_DIM + jg)) * 128 + zz] =
                    zacc[zi][pf][cc] + bf[zi][(cc >> 1) & 1];
            }
}

// ---------------------------------------------------------------- launch
extern "C" void kernel_launch(void* const* d_in, const int* in_sizes, int n_in,
                              void* d_out, int out_size)
{
    const float* m_si    = (const float*)d_in[0];
    const float* ln_g    = (const float*)d_in[1];
    const float* ln_b    = (const float*)d_in[2];
    const float* w_ab    = (const float*)d_in[3];
    const float* w_final = (const float*)d_in[4];
    const float* b_final = (const float*)d_in[5];
    float* z = (float*)d_out;
    (void)in_sizes; (void)n_in; (void)out_size;

    ln_proj_kernel<<<3072, 256>>>(m_si, ln_g, ln_b, w_ab, w_final);

    cudaFuncSetAttribute(opm_mma_kernel,
                         cudaFuncAttributeMaxDynamicSharedMemorySize, SMEM2);
    dim3 grid(48, 96);   // (8-j tiles, 4-i tiles)
    opm_mma_kernel<<<grid, 128, SMEM2>>>(b_final, z);
}